// round 12
// baseline (speedup 1.0000x reference)
#include <cuda_runtime.h>
#include <cuda_fp16.h>
#include <cstdint>
#include <cstddef>

#define DIM 512
#define MAXA 100000
#define KPA 192

// ---------------- scratch (static device globals; no allocation) ----------------
__device__ float g_msg [(size_t)MAXA * DIM];
__device__ float g_f32a[(size_t)MAXA * DIM];
__device__ float g_f32b[(size_t)MAXA * DIM];
__device__ float g_bias[(size_t)MAXA * DIM];
// activation planes: hi[...] then lo[...]  (fp16)
__device__ __align__(16) __half g_pa [(size_t)2 * MAXA * KPA];
__device__ __align__(16) __half g_pg [(size_t)2 * MAXA * DIM];
__device__ __align__(16) __half g_p0 [(size_t)2 * MAXA * DIM];
__device__ __align__(16) __half g_p1 [(size_t)2 * MAXA * DIM];
__device__ __align__(16) __half g_pcc[(size_t)2 * MAXA * DIM];
// transposed fp16 weights: [512][Kp] single plane per GEMM
__device__ __align__(16) __half g_wt[2031616];

// ---------------- helpers ----------------
__device__ __forceinline__ uint32_t s2u(const void* p) {
    uint32_t a;
    asm("{ .reg .u64 t; cvta.to.shared.u64 t, %1; cvt.u32.u64 %0, t; }" : "=r"(a) : "l"(p));
    return a;
}

// SW64-style swizzle for 64B rows: XOR bits[5:4] with bits[9:8]
#define SWZ(a) ((a) ^ (((a) >> 3) & 0x30u))

#define CP16(dst, src) \
    asm volatile("cp.async.cg.shared.global [%0], [%1], 16;" :: "r"(dst), "l"(src) : "memory")
#define CP_COMMIT() asm volatile("cp.async.commit_group;" ::: "memory")
#define CP_WAIT1()  asm volatile("cp.async.wait_group 1;" ::: "memory")

#define LDSM4(r, addr) \
    asm volatile("ldmatrix.sync.aligned.m8n8.x4.shared.b16 {%0,%1,%2,%3}, [%4];" \
        : "=r"((r)[0]), "=r"((r)[1]), "=r"((r)[2]), "=r"((r)[3]) : "r"(addr))

#define MMA16816(d, a, b0, b1) \
    asm volatile("mma.sync.aligned.m16n8k16.row.col.f32.f16.f16.f32 " \
        "{%0,%1,%2,%3}, {%4,%5,%6,%7}, {%8,%9}, {%0,%1,%2,%3};" \
        : "+f"((d)[0]), "+f"((d)[1]), "+f"((d)[2]), "+f"((d)[3]) \
        : "r"((a)[0]), "r"((a)[1]), "r"((a)[2]), "r"((a)[3]), "r"(b0), "r"(b1))

__device__ __forceinline__ void split2h(float a0, float a1, uint32_t& h, uint32_t& l) {
    __half h0 = __float2half(a0);
    __half h1 = __float2half(a1);
    __half b0 = __float2half(a0 - __half2float(h0));
    __half b1 = __float2half(a1 - __half2float(h1));
    h = (uint32_t)__half_as_ushort(h0) | ((uint32_t)__half_as_ushort(h1) << 16);
    l = (uint32_t)__half_as_ushort(b0) | ((uint32_t)__half_as_ushort(b1) << 16);
}

// ---------------- fused prep: atoms planes + all 9 weight transposes ----------------
__global__ void prep_all(const float* __restrict__ fa,
    const float* __restrict__ W_i,  const float* __restrict__ Wah0,
    const float* __restrict__ Wah1, const float* __restrict__ Wah2,
    const float* __restrict__ Wh0,  const float* __restrict__ Wh1,
    const float* __restrict__ Wh2,  const float* __restrict__ Wot,
    const float* __restrict__ Wob,
    __half* __restrict__ wt, __half* __restrict__ pa, int M)
{
    const int tid0 = blockIdx.x * blockDim.x + threadIdx.x;
    const int stride = gridDim.x * blockDim.x;

    __half* lo = pa + (size_t)MAXA * KPA;
    for (int idx = tid0; idx < M * KPA; idx += stride) {
        int row = idx / KPA, k = idx - row * KPA;
        float v = (k < 133) ? fa[(size_t)row * 133 + k] : 0.f;
        __half h = __float2half(v);
        pa[idx] = h;
        lo[idx] = __float2half(v - __half2float(h));
    }

    const float* srcs[9] = {W_i, Wah0, Wah1, Wah2, Wh0, Wh1, Wh2, Wot, Wob};
    const int    kre[9]  = {133, 133, 512, 512, 512, 512, 512, 512, 512};
    const int    kps[9]  = {KPA, KPA, 512, 512, 512, 512, 512, 512, 512};
    size_t off = 0;
    #pragma unroll 1
    for (int t = 0; t < 9; t++) {
        const int Kp = kps[t], total = 512 * Kp, kr = kre[t];
        const float* W = srcs[t];
        __half* out = wt + off;
        for (int idx = tid0; idx < total; idx += stride) {
            int n = idx / Kp, k = idx - n * Kp;
            float v = (k < kr) ? W[(size_t)k * 512 + n] : 0.f;
            out[idx] = __float2half(v);
        }
        off += total;
    }
}

// ---------------- HMMA GEMM: out = f(A @ W + bias + add), 2-term fp16 ------------------
// A = Ahi + Alo (fp16 planes), W single fp16 plane. D = Ahi*W + Alo*W (fp32 accum).
// CTA tile 128M x 128N, BK=32, grid (4, ceil(M/128)), 256 threads, warp tile 32x64.
// 2-stage cp.async pipeline, SWIZZLED 64B rows (no padding) -> smem 49152 B, 4 CTAs/SM.
// stage s @ s*24576: A hi@0 (8192), A lo@8192, B @16384 (8192).
template<bool RELU_OUT, bool EMIT_PLANES>
__global__ void __launch_bounds__(256, 4) gemm_mma(
    const __half* __restrict__ Ahi, size_t APL,
    const __half* __restrict__ Wp,
    const float* __restrict__ bias, const float* __restrict__ addf,
    float* __restrict__ Cf, __half* __restrict__ Cp,
    int M, int Kp, int zero_row0)
{
    extern __shared__ __align__(16) char smem[];
    const uint32_t sb = s2u(smem);
    const uint32_t A_PLN = 8192, B_OFF = 16384, STG = 24576;
    const size_t PPL = (size_t)MAXA * DIM;

    const __half* Alo = Ahi + APL;
    const int tid = threadIdx.x, lane = tid & 31, wid = tid >> 5;
    const int wm = wid >> 1, wn = wid & 1;    // warp grid 4x2, warp tile 32M x 64N
    const int row0 = blockIdx.y * 128, col0 = blockIdx.x * 128;
    const int nch = Kp >> 5;                  // BK=32 chunks

    float acc[2][8][4];
    #pragma unroll
    for (int i = 0; i < 2; i++)
        #pragma unroll
        for (int j = 0; j < 8; j++)
            #pragma unroll
            for (int q = 0; q < 4; q++) acc[i][j][q] = 0.f;

    // loaders: 2 threads/row (128 rows), 16 elems (32 B) each
    const int lr = tid >> 1, seg = (tid & 1) * 16;        // elem offset 0/16
    const int agrow = row0 + lr;
    const uint32_t dlog = (uint32_t)lr * 64 + (uint32_t)seg * 2;   // logical byte offset
    const uint32_t d0 = SWZ(dlog), d1 = SWZ(dlog + 16);

    auto issue = [&](int c, int buf) {
        uint32_t base = sb + (uint32_t)buf * STG;
        if (agrow < M) {
            const __half* s  = Ahi + (size_t)agrow * Kp + c * 32 + seg;
            const __half* s2 = Alo + (size_t)agrow * Kp + c * 32 + seg;
            CP16(base + d0, s);             CP16(base + d1, s + 8);
            CP16(base + A_PLN + d0, s2);    CP16(base + A_PLN + d1, s2 + 8);
        }
        {
            const __half* s = Wp + (size_t)(col0 + lr) * Kp + c * 32 + seg;
            CP16(base + B_OFF + d0, s);     CP16(base + B_OFF + d1, s + 8);
        }
    };

    // ldmatrix logical row-base offsets (swizzle applied per access)
    const uint32_t a_log0 = (uint32_t)(wm * 32 + (lane & 15)) * 64 + (uint32_t)(lane >> 4) * 16;
    const uint32_t b_log0 = (uint32_t)(wn * 64 + (lane & 7) + ((lane >> 4) & 1) * 8) * 64
                            + (uint32_t)((lane >> 3) & 1) * 16;

    issue(0, 0);
    CP_COMMIT();

    for (int c = 0; c < nch; c++) {
        if (c + 1 < nch) issue(c + 1, (c + 1) & 1);
        CP_COMMIT();
        CP_WAIT1();
        __syncthreads();

        const uint32_t sbase = sb + (uint32_t)(c & 1) * STG;
        #pragma unroll
        for (int ks = 0; ks < 2; ks++) {
            uint32_t ah[2][4], al[2][4];
            #pragma unroll
            for (int mt = 0; mt < 2; mt++) {
                uint32_t alog = a_log0 + mt * 16 * 64 + ks * 32;
                uint32_t aa = sbase + SWZ(alog);
                LDSM4(ah[mt], aa);
                LDSM4(al[mt], aa + A_PLN);   // A_PLN is 8192: swizzle bits unaffected
            }
            #pragma unroll
            for (int ntp = 0; ntp < 4; ntp++) {
                uint32_t bh[4];
                uint32_t blog = b_log0 + ntp * 16 * 64 + ks * 32;
                LDSM4(bh, sbase + B_OFF + SWZ(blog));
                #pragma unroll
                for (int h = 0; h < 2; h++) {
                    const int nt = ntp * 2 + h;
                    #pragma unroll
                    for (int mt = 0; mt < 2; mt++) {
                        MMA16816(acc[mt][nt], ah[mt], bh[2 * h], bh[2 * h + 1]);
                        MMA16816(acc[mt][nt], al[mt], bh[2 * h], bh[2 * h + 1]);
                    }
                }
            }
        }
        __syncthreads();
    }

    // ---- epilogue ----
    const int g = lane >> 2, tg = lane & 3;
    #pragma unroll
    for (int mt = 0; mt < 2; mt++) {
        #pragma unroll
        for (int nt = 0; nt < 8; nt++) {
            const int col = col0 + wn * 64 + nt * 8 + tg * 2;
            #pragma unroll
            for (int half = 0; half < 2; half++) {
                const int row = row0 + wm * 32 + mt * 16 + g + half * 8;
                if (row >= M) continue;
                float v0 = acc[mt][nt][half * 2 + 0];
                float v1 = acc[mt][nt][half * 2 + 1];
                if (bias) {
                    const float2 bv = *(const float2*)(bias + col);
                    v0 += bv.x; v1 += bv.y;
                }
                if (addf) {
                    const float2 av = *(const float2*)(addf + (size_t)row * DIM + col);
                    v0 += av.x; v1 += av.y;
                }
                if (RELU_OUT) { v0 = fmaxf(v0, 0.f); v1 = fmaxf(v1, 0.f); }
                if (zero_row0 && row == 0) { v0 = 0.f; v1 = 0.f; }
                if (EMIT_PLANES) {
                    uint32_t hp, lp;
                    split2h(v0, v1, hp, lp);
                    *(uint32_t*)(Cp + (size_t)row * DIM + col) = hp;
                    *(uint32_t*)(Cp + PPL + (size_t)row * DIM + col) = lp;
                } else {
                    *(float2*)(Cf + (size_t)row * DIM + col) = make_float2(v0, v1);
                }
            }
        }
    }
}

// ---------------- gather-sum + optional relu + split to fp16 planes ----------------
template<bool RELU>
__global__ void gather_split(const float* __restrict__ src, const int* __restrict__ a2a,
                             __half* __restrict__ hi)
{
    const size_t PPL = (size_t)MAXA * DIM;
    const int atom = blockIdx.x;
    const int t = threadIdx.x;                 // 128 threads x 4 floats
    const int* idx = a2a + (size_t)atom * 6;
    float4 acc = make_float4(0.f, 0.f, 0.f, 0.f);
    #pragma unroll
    for (int j = 0; j < 6; j++) {
        const float4 v = *(const float4*)(src + (size_t)idx[j] * DIM + t * 4);
        acc.x += v.x; acc.y += v.y; acc.z += v.z; acc.w += v.w;
    }
    if (RELU) {
        acc.x = fmaxf(acc.x, 0.f); acc.y = fmaxf(acc.y, 0.f);
        acc.z = fmaxf(acc.z, 0.f); acc.w = fmaxf(acc.w, 0.f);
    }
    uint32_t h0, l0, h1, l1;
    split2h(acc.x, acc.y, h0, l0);
    split2h(acc.z, acc.w, h1, l1);
    *(uint2*)(hi + (size_t)atom * DIM + t * 4)       = make_uint2(h0, h1);
    *(uint2*)(hi + PPL + (size_t)atom * DIM + t * 4) = make_uint2(l0, l1);
}

// ---------------- bond bias ----------------
__global__ void bond_bias_kernel(const float* __restrict__ f_bonds, const int* __restrict__ a2b,
                                 const float* __restrict__ Wb, const float* __restrict__ b0,
                                 float* __restrict__ dst)
{
    const int atom = blockIdx.x;
    const int t = threadIdx.x;
    __shared__ float bs[14];
    if (t < 14) {
        const int* idx = a2b + (size_t)atom * 6;
        float s = 0.f;
        #pragma unroll
        for (int j = 0; j < 6; j++) s += f_bonds[(size_t)idx[j] * 14 + t];
        bs[t] = fmaxf(s, 0.f);
    }
    __syncthreads();
    #pragma unroll
    for (int rr = 0; rr < 4; rr++) {
        int n = t + rr * 128;
        float acc = b0[n];
        #pragma unroll
        for (int k = 0; k < 14; k++) acc = fmaf(bs[k], Wb[k * DIM + n], acc);
        dst[(size_t)atom * DIM + n] = acc;
    }
}

// ---------------- segment sum via atomics ----------------
__global__ void segment_atomic(const float* __restrict__ x, const int* __restrict__ mol_ids,
                               float* __restrict__ out, int n_mols)
{
    const int atom = blockIdx.x;
    const int mid = mol_ids[atom];
    if (mid < 0 || mid >= n_mols) return;
    const int t = threadIdx.x;
    #pragma unroll
    for (int rr = 0; rr < 4; rr++) {
        int n = t + rr * 128;
        atomicAdd(out + (size_t)mid * DIM + n, x[(size_t)atom * DIM + n]);
    }
}

extern "C" void kernel_launch(void* const* d_in, const int* in_sizes, int n_in,
                              void* d_out, int out_size)
{
    const float* f_atoms = (const float*)d_in[0];
    const float* f_bonds = (const float*)d_in[1];
    const int*   a2a     = (const int*)d_in[2];
    const int*   a2b     = (const int*)d_in[3];
    const int*   mol_ids = (const int*)d_in[4];
    const int base = n_in - 16;
    const float* W_i_w  = (const float*)d_in[base + 0];
    const float* W_i_b  = (const float*)d_in[base + 1];
    const float* Wh0_w  = (const float*)d_in[base + 2];
    const float* Wh0_b  = (const float*)d_in[base + 3];
    const float* Wh1_w  = (const float*)d_in[base + 4];
    const float* Wh1_b  = (const float*)d_in[base + 5];
    const float* Wh2_w  = (const float*)d_in[base + 6];
    const float* Wh2_b  = (const float*)d_in[base + 7];
    const float* Wah0_w = (const float*)d_in[base + 8];
    const float* Wah0_b = (const float*)d_in[base + 9];
    const float* Wah1_w = (const float*)d_in[base + 10];
    const float* Wah1_b = (const float*)d_in[base + 11];
    const float* Wah2_w = (const float*)d_in[base + 12];
    const float* Wah2_b = (const float*)d_in[base + 13];
    const float* W_o_w  = (const float*)d_in[base + 14];
    const float* W_o_b  = (const float*)d_in[base + 15];

    const int M      = in_sizes[0] / 133;
    const int n_mols = out_size / DIM;

    float *p_msg, *p_f32a, *p_f32b, *p_bias;
    __half *p_pa, *p_pg, *p_p0, *p_p1, *p_pcc, *p_wt;
    cudaGetSymbolAddress((void**)&p_msg,  g_msg);
    cudaGetSymbolAddress((void**)&p_f32a, g_f32a);
    cudaGetSymbolAddress((void**)&p_f32b, g_f32b);
    cudaGetSymbolAddress((void**)&p_bias, g_bias);
    cudaGetSymbolAddress((void**)&p_pa,   g_pa);
    cudaGetSymbolAddress((void**)&p_pg,   g_pg);
    cudaGetSymbolAddress((void**)&p_p0,   g_p0);
    cudaGetSymbolAddress((void**)&p_p1,   g_p1);
    cudaGetSymbolAddress((void**)&p_pcc,  g_pcc);
    cudaGetSymbolAddress((void**)&p_wt,   g_wt);

    // weight offsets in fp16 elements — matches prep_all order
    const size_t OFF_WI   = 0;
    const size_t OFF_WAH0 = 98304;
    const size_t OFF_WAH1 = 196608;
    const size_t OFF_WAH2 = 458752;
    const size_t OFF_WH0  = 720896;
    const size_t OFF_WH1  = 983040;
    const size_t OFF_WH2  = 1245184;
    const size_t OFF_WOT  = 1507328;
    const size_t OFF_WOB  = 1769472;

    const int SMEM_BYTES = 49152;
    cudaFuncSetAttribute(gemm_mma<true,  true >, cudaFuncAttributeMaxDynamicSharedMemorySize, SMEM_BYTES);
    cudaFuncSetAttribute(gemm_mma<true,  false>, cudaFuncAttributeMaxDynamicSharedMemorySize, SMEM_BYTES);
    cudaFuncSetAttribute(gemm_mma<false, false>, cudaFuncAttributeMaxDynamicSharedMemorySize, SMEM_BYTES);

    const dim3 gg(4, (M + 127) / 128);
    const size_t APL_A = (size_t)MAXA * KPA;
    const size_t APL_D = (size_t)MAXA * DIM;

    // launch 0: ALL prep fused
    prep_all<<<1024, 256>>>(f_atoms, W_i_w, Wah0_w, Wah1_w, Wah2_w,
                            Wh0_w, Wh1_w, Wh2_w, W_o_w, W_o_w + (size_t)DIM * DIM,
                            p_wt, p_pa, M);

    // launches 1-3: cc chain (GEMMs — ncu capture lands here)
    gemm_mma<true, true><<<gg, 256, SMEM_BYTES>>>(
        p_pa, APL_A, p_wt + OFF_WAH0, Wah0_b, nullptr, nullptr, p_p0, M, KPA, 0);
    gemm_mma<true, true><<<gg, 256, SMEM_BYTES>>>(
        p_p0, APL_D, p_wt + OFF_WAH1, Wah1_b, nullptr, nullptr, p_p1, M, 512, 0);
    gemm_mma<true, true><<<gg, 256, SMEM_BYTES>>>(
        p_p1, APL_D, p_wt + OFF_WAH2, Wah2_b, nullptr, nullptr, p_pcc, M, 512, 0);

    // msg = relu(f_atoms @ W_i + b_i), row0 zeroed -> fp32
    gemm_mma<true, false><<<gg, 256, SMEM_BYTES>>>(
        p_pa, APL_A, p_wt + OFF_WI, W_i_b, nullptr, p_msg, nullptr, M, KPA, 1);

    bond_bias_kernel<<<M, 128>>>(f_bonds, a2b, Wh0_w + (size_t)DIM * DIM, Wh0_b, p_bias);

    for (int d = 0; d < 4; d++) {
        gather_split<true><<<M, 128>>>(p_msg, a2a, p_pg);
        gemm_mma<true, true><<<gg, 256, SMEM_BYTES>>>(
            p_pg, APL_D, p_wt + OFF_WH0, nullptr, p_bias, nullptr, p_p0, M, 512, 0);
        gemm_mma<true, true><<<gg, 256, SMEM_BYTES>>>(
            p_p0, APL_D, p_wt + OFF_WH1, Wh1_b, nullptr, nullptr, p_p1, M, 512, 0);
        gemm_mma<false, false><<<gg, 256, SMEM_BYTES>>>(
            p_p1, APL_D, p_wt + OFF_WH2, Wh2_b, p_msg, p_msg, nullptr, M, 512, 1);
    }

    // a_message planes (NO relu)
    gather_split<false><<<M, 128>>>(p_msg, a2a, p_pg);

    cudaMemsetAsync(d_out, 0, (size_t)out_size * sizeof(float), 0);

    // out = relu(cc @ Wo_top + a_message @ Wo_bot + b_o)
    gemm_mma<false, false><<<gg, 256, SMEM_BYTES>>>(
        p_pcc, APL_D, p_wt + OFF_WOT, W_o_b, nullptr, p_f32a, nullptr, M, 512, 0);
    gemm_mma<true, false><<<gg, 256, SMEM_BYTES>>>(
        p_pg, APL_D, p_wt + OFF_WOB, nullptr, p_f32a, p_f32b, nullptr, M, 512, 0);

    segment_atomic<<<M, 128>>>(p_f32b, mol_ids, (float*)d_out, n_mols);
}

// round 13
// speedup vs baseline: 2.7007x; 2.7007x over previous
#include <cuda_runtime.h>
#include <cuda_fp16.h>
#include <cstdint>
#include <cstddef>

#define DIM 512
#define MAXA 100000
#define KPA 192

// ---------------- scratch (static device globals; no allocation) ----------------
__device__ float g_msg [(size_t)MAXA * DIM];
__device__ float g_f32a[(size_t)MAXA * DIM];
__device__ float g_f32b[(size_t)MAXA * DIM];
__device__ float g_bias[(size_t)MAXA * DIM];
// fp16 activation buffers (single plane)
__device__ __align__(16) __half g_pa [(size_t)MAXA * KPA];
__device__ __align__(16) __half g_pg [(size_t)MAXA * DIM];
__device__ __align__(16) __half g_p0 [(size_t)MAXA * DIM];
__device__ __align__(16) __half g_p1 [(size_t)MAXA * DIM];
__device__ __align__(16) __half g_pcc[(size_t)MAXA * DIM];
// transposed fp16 weights: [512][Kp] single plane per GEMM
__device__ __align__(16) __half g_wt[2031616];

// ---------------- helpers ----------------
__device__ __forceinline__ uint32_t s2u(const void* p) {
    uint32_t a;
    asm("{ .reg .u64 t; cvta.to.shared.u64 t, %1; cvt.u32.u64 %0, t; }" : "=r"(a) : "l"(p));
    return a;
}

#define CP16(dst, src) \
    asm volatile("cp.async.cg.shared.global [%0], [%1], 16;" :: "r"(dst), "l"(src) : "memory")
#define CP_COMMIT() asm volatile("cp.async.commit_group;" ::: "memory")
#define CP_WAIT1()  asm volatile("cp.async.wait_group 1;" ::: "memory")

#define LDSM4(r, addr) \
    asm volatile("ldmatrix.sync.aligned.m8n8.x4.shared.b16 {%0,%1,%2,%3}, [%4];" \
        : "=r"((r)[0]), "=r"((r)[1]), "=r"((r)[2]), "=r"((r)[3]) : "r"(addr))

#define MMA16816(d, a, b0, b1) \
    asm volatile("mma.sync.aligned.m16n8k16.row.col.f32.f16.f16.f32 " \
        "{%0,%1,%2,%3}, {%4,%5,%6,%7}, {%8,%9}, {%0,%1,%2,%3};" \
        : "+f"((d)[0]), "+f"((d)[1]), "+f"((d)[2]), "+f"((d)[3]) \
        : "r"((a)[0]), "r"((a)[1]), "r"((a)[2]), "r"((a)[3]), "r"(b0), "r"(b1))

// ---------------- fused prep: atoms fp16 + all 9 weight transposes ----------------
__global__ void prep_all(const float* __restrict__ fa,
    const float* __restrict__ W_i,  const float* __restrict__ Wah0,
    const float* __restrict__ Wah1, const float* __restrict__ Wah2,
    const float* __restrict__ Wh0,  const float* __restrict__ Wh1,
    const float* __restrict__ Wh2,  const float* __restrict__ Wot,
    const float* __restrict__ Wob,
    __half* __restrict__ wt, __half* __restrict__ pa, int M)
{
    const int tid0 = blockIdx.x * blockDim.x + threadIdx.x;
    const int stride = gridDim.x * blockDim.x;

    for (int idx = tid0; idx < M * KPA; idx += stride) {
        int row = idx / KPA, k = idx - row * KPA;
        float v = (k < 133) ? fa[(size_t)row * 133 + k] : 0.f;
        pa[idx] = __float2half(v);
    }

    const float* srcs[9] = {W_i, Wah0, Wah1, Wah2, Wh0, Wh1, Wh2, Wot, Wob};
    const int    kre[9]  = {133, 133, 512, 512, 512, 512, 512, 512, 512};
    const int    kps[9]  = {KPA, KPA, 512, 512, 512, 512, 512, 512, 512};
    size_t off = 0;
    #pragma unroll 1
    for (int t = 0; t < 9; t++) {
        const int Kp = kps[t], total = 512 * Kp, kr = kre[t];
        const float* W = srcs[t];
        __half* out = wt + off;
        for (int idx = tid0; idx < total; idx += stride) {
            int n = idx / Kp, k = idx - n * Kp;
            float v = (k < kr) ? W[(size_t)k * 512 + n] : 0.f;
            out[idx] = __float2half(v);
        }
        off += total;
    }
}

// ---------------- HMMA GEMM: out = f(A @ W + bias + add), pure fp16 -------------------
// CTA tile 128M x 128N, BK=64, grid (4, ceil(M/128)), 256 threads, warp tile 32x64.
// 2-stage cp.async pipeline, smem 73728 B (stage 36864: A@0 18432, B@18432), 2 CTAs/SM.
// Rows 144 B (128 data + 16 pad) -> conflict-free ldmatrix.
template<bool RELU_OUT, bool EMIT_H>
__global__ void __launch_bounds__(256, 2) gemm_mma(
    const __half* __restrict__ A,
    const __half* __restrict__ Wp,
    const float* __restrict__ bias, const float* __restrict__ addf,
    float* __restrict__ Cf, __half* __restrict__ Cp,
    int M, int Kp, int zero_row0)
{
    extern __shared__ __align__(16) char smem[];
    const uint32_t sb = s2u(smem);
    const uint32_t RS = 144;
    const uint32_t B_OFF = 18432, STG = 36864;

    const int tid = threadIdx.x, lane = tid & 31, wid = tid >> 5;
    const int wm = wid >> 1, wn = wid & 1;    // warp grid 4x2, warp tile 32M x 64N
    const int row0 = blockIdx.y * 128, col0 = blockIdx.x * 128;
    const int nch = Kp >> 6;

    float acc[2][8][4];
    #pragma unroll
    for (int i = 0; i < 2; i++)
        #pragma unroll
        for (int j = 0; j < 8; j++)
            #pragma unroll
            for (int q = 0; q < 4; q++) acc[i][j][q] = 0.f;

    // loaders: 2 threads/row (128 rows), 32 elems (64 B) each
    const int lr = tid >> 1, seg = (tid & 1) * 32;
    const int agrow = row0 + lr;
    const uint32_t dst = (uint32_t)lr * RS + (uint32_t)seg * 2;

    auto issue = [&](int c, int buf) {
        uint32_t base = sb + (uint32_t)buf * STG;
        if (agrow < M) {
            const __half* s = A + (size_t)agrow * Kp + c * 64 + seg;
            uint32_t d = base + dst;
            CP16(d, s);            CP16(d + 16, s + 8);
            CP16(d + 32, s + 16);  CP16(d + 48, s + 24);
        }
        {
            const __half* s = Wp + (size_t)(col0 + lr) * Kp + c * 64 + seg;
            uint32_t d = base + B_OFF + dst;
            CP16(d, s);            CP16(d + 16, s + 8);
            CP16(d + 32, s + 16);  CP16(d + 48, s + 24);
        }
    };

    // ldmatrix constant offsets
    const uint32_t a_off = (uint32_t)(wm * 32 + (lane & 15)) * RS + (uint32_t)(lane >> 4) * 16;
    const uint32_t b_off = (uint32_t)(wn * 64 + (lane & 7) + ((lane >> 4) & 1) * 8) * RS
                           + (uint32_t)((lane >> 3) & 1) * 16;

    issue(0, 0);
    CP_COMMIT();

    for (int c = 0; c < nch; c++) {
        if (c + 1 < nch) issue(c + 1, (c + 1) & 1);
        CP_COMMIT();
        CP_WAIT1();
        __syncthreads();

        const uint32_t sbase = sb + (uint32_t)(c & 1) * STG;
        const uint32_t abase = sbase + a_off;
        const uint32_t bbase = sbase + B_OFF + b_off;
        #pragma unroll
        for (int ks = 0; ks < 4; ks++) {
            uint32_t ah[2][4];
            #pragma unroll
            for (int mt = 0; mt < 2; mt++)
                LDSM4(ah[mt], abase + mt * 16 * RS + ks * 32);
            #pragma unroll
            for (int ntp = 0; ntp < 4; ntp++) {
                uint32_t bh[4];
                LDSM4(bh, bbase + ntp * 16 * RS + ks * 32);
                #pragma unroll
                for (int h = 0; h < 2; h++) {
                    const int nt = ntp * 2 + h;
                    #pragma unroll
                    for (int mt = 0; mt < 2; mt++)
                        MMA16816(acc[mt][nt], ah[mt], bh[2 * h], bh[2 * h + 1]);
                }
            }
        }
        __syncthreads();
    }

    // ---- epilogue ----
    const int g = lane >> 2, tg = lane & 3;
    #pragma unroll
    for (int mt = 0; mt < 2; mt++) {
        #pragma unroll
        for (int nt = 0; nt < 8; nt++) {
            const int col = col0 + wn * 64 + nt * 8 + tg * 2;
            #pragma unroll
            for (int half = 0; half < 2; half++) {
                const int row = row0 + wm * 32 + mt * 16 + g + half * 8;
                if (row >= M) continue;
                float v0 = acc[mt][nt][half * 2 + 0];
                float v1 = acc[mt][nt][half * 2 + 1];
                if (bias) {
                    const float2 bv = *(const float2*)(bias + col);
                    v0 += bv.x; v1 += bv.y;
                }
                if (addf) {
                    const float2 av = *(const float2*)(addf + (size_t)row * DIM + col);
                    v0 += av.x; v1 += av.y;
                }
                if (RELU_OUT) { v0 = fmaxf(v0, 0.f); v1 = fmaxf(v1, 0.f); }
                if (zero_row0 && row == 0) { v0 = 0.f; v1 = 0.f; }
                if (EMIT_H) {
                    __half2 hp = __floats2half2_rn(v0, v1);
                    *(__half2*)(Cp + (size_t)row * DIM + col) = hp;
                } else {
                    *(float2*)(Cf + (size_t)row * DIM + col) = make_float2(v0, v1);
                }
            }
        }
    }
}

// ---------------- gather-sum + optional relu -> fp16 ----------------
template<bool RELU>
__global__ void gather_h(const float* __restrict__ src, const int* __restrict__ a2a,
                         __half* __restrict__ out)
{
    const int atom = blockIdx.x;
    const int t = threadIdx.x;                 // 128 threads x 4 floats
    const int* idx = a2a + (size_t)atom * 6;
    float4 acc = make_float4(0.f, 0.f, 0.f, 0.f);
    #pragma unroll
    for (int j = 0; j < 6; j++) {
        const float4 v = *(const float4*)(src + (size_t)idx[j] * DIM + t * 4);
        acc.x += v.x; acc.y += v.y; acc.z += v.z; acc.w += v.w;
    }
    if (RELU) {
        acc.x = fmaxf(acc.x, 0.f); acc.y = fmaxf(acc.y, 0.f);
        acc.z = fmaxf(acc.z, 0.f); acc.w = fmaxf(acc.w, 0.f);
    }
    __half2 h0 = __floats2half2_rn(acc.x, acc.y);
    __half2 h1 = __floats2half2_rn(acc.z, acc.w);
    *(__half2*)(out + (size_t)atom * DIM + t * 4)     = h0;
    *(__half2*)(out + (size_t)atom * DIM + t * 4 + 2) = h1;
}

// ---------------- bond bias ----------------
__global__ void bond_bias_kernel(const float* __restrict__ f_bonds, const int* __restrict__ a2b,
                                 const float* __restrict__ Wb, const float* __restrict__ b0,
                                 float* __restrict__ dst)
{
    const int atom = blockIdx.x;
    const int t = threadIdx.x;
    __shared__ float bs[14];
    if (t < 14) {
        const int* idx = a2b + (size_t)atom * 6;
        float s = 0.f;
        #pragma unroll
        for (int j = 0; j < 6; j++) s += f_bonds[(size_t)idx[j] * 14 + t];
        bs[t] = fmaxf(s, 0.f);
    }
    __syncthreads();
    #pragma unroll
    for (int rr = 0; rr < 4; rr++) {
        int n = t + rr * 128;
        float acc = b0[n];
        #pragma unroll
        for (int k = 0; k < 14; k++) acc = fmaf(bs[k], Wb[k * DIM + n], acc);
        dst[(size_t)atom * DIM + n] = acc;
    }
}

// ---------------- segment sum via atomics ----------------
__global__ void segment_atomic(const float* __restrict__ x, const int* __restrict__ mol_ids,
                               float* __restrict__ out, int n_mols)
{
    const int atom = blockIdx.x;
    const int mid = mol_ids[atom];
    if (mid < 0 || mid >= n_mols) return;
    const int t = threadIdx.x;
    #pragma unroll
    for (int rr = 0; rr < 4; rr++) {
        int n = t + rr * 128;
        atomicAdd(out + (size_t)mid * DIM + n, x[(size_t)atom * DIM + n]);
    }
}

extern "C" void kernel_launch(void* const* d_in, const int* in_sizes, int n_in,
                              void* d_out, int out_size)
{
    const float* f_atoms = (const float*)d_in[0];
    const float* f_bonds = (const float*)d_in[1];
    const int*   a2a     = (const int*)d_in[2];
    const int*   a2b     = (const int*)d_in[3];
    const int*   mol_ids = (const int*)d_in[4];
    const int base = n_in - 16;
    const float* W_i_w  = (const float*)d_in[base + 0];
    const float* W_i_b  = (const float*)d_in[base + 1];
    const float* Wh0_w  = (const float*)d_in[base + 2];
    const float* Wh0_b  = (const float*)d_in[base + 3];
    const float* Wh1_w  = (const float*)d_in[base + 4];
    const float* Wh1_b  = (const float*)d_in[base + 5];
    const float* Wh2_w  = (const float*)d_in[base + 6];
    const float* Wh2_b  = (const float*)d_in[base + 7];
    const float* Wah0_w = (const float*)d_in[base + 8];
    const float* Wah0_b = (const float*)d_in[base + 9];
    const float* Wah1_w = (const float*)d_in[base + 10];
    const float* Wah1_b = (const float*)d_in[base + 11];
    const float* Wah2_w = (const float*)d_in[base + 12];
    const float* Wah2_b = (const float*)d_in[base + 13];
    const float* W_o_w  = (const float*)d_in[base + 14];
    const float* W_o_b  = (const float*)d_in[base + 15];

    const int M      = in_sizes[0] / 133;
    const int n_mols = out_size / DIM;

    float *p_msg, *p_f32a, *p_f32b, *p_bias;
    __half *p_pa, *p_pg, *p_p0, *p_p1, *p_pcc, *p_wt;
    cudaGetSymbolAddress((void**)&p_msg,  g_msg);
    cudaGetSymbolAddress((void**)&p_f32a, g_f32a);
    cudaGetSymbolAddress((void**)&p_f32b, g_f32b);
    cudaGetSymbolAddress((void**)&p_bias, g_bias);
    cudaGetSymbolAddress((void**)&p_pa,   g_pa);
    cudaGetSymbolAddress((void**)&p_pg,   g_pg);
    cudaGetSymbolAddress((void**)&p_p0,   g_p0);
    cudaGetSymbolAddress((void**)&p_p1,   g_p1);
    cudaGetSymbolAddress((void**)&p_pcc,  g_pcc);
    cudaGetSymbolAddress((void**)&p_wt,   g_wt);

    // weight offsets in fp16 elements — matches prep_all order
    const size_t OFF_WI   = 0;
    const size_t OFF_WAH0 = 98304;
    const size_t OFF_WAH1 = 196608;
    const size_t OFF_WAH2 = 458752;
    const size_t OFF_WH0  = 720896;
    const size_t OFF_WH1  = 983040;
    const size_t OFF_WH2  = 1245184;
    const size_t OFF_WOT  = 1507328;
    const size_t OFF_WOB  = 1769472;

    const int SMEM_BYTES = 73728;
    cudaFuncSetAttribute(gemm_mma<true,  true >, cudaFuncAttributeMaxDynamicSharedMemorySize, SMEM_BYTES);
    cudaFuncSetAttribute(gemm_mma<true,  false>, cudaFuncAttributeMaxDynamicSharedMemorySize, SMEM_BYTES);
    cudaFuncSetAttribute(gemm_mma<false, false>, cudaFuncAttributeMaxDynamicSharedMemorySize, SMEM_BYTES);

    const dim3 gg(4, (M + 127) / 128);

    // launch 0: ALL prep fused
    prep_all<<<1024, 256>>>(f_atoms, W_i_w, Wah0_w, Wah1_w, Wah2_w,
                            Wh0_w, Wh1_w, Wh2_w, W_o_w, W_o_w + (size_t)DIM * DIM,
                            p_wt, p_pa, M);

    // launches 1-3: cc chain (GEMMs — ncu capture lands here)
    gemm_mma<true, true><<<gg, 256, SMEM_BYTES>>>(
        p_pa, p_wt + OFF_WAH0, Wah0_b, nullptr, nullptr, p_p0, M, KPA, 0);
    gemm_mma<true, true><<<gg, 256, SMEM_BYTES>>>(
        p_p0, p_wt + OFF_WAH1, Wah1_b, nullptr, nullptr, p_p1, M, 512, 0);
    gemm_mma<true, true><<<gg, 256, SMEM_BYTES>>>(
        p_p1, p_wt + OFF_WAH2, Wah2_b, nullptr, nullptr, p_pcc, M, 512, 0);

    // msg = relu(f_atoms @ W_i + b_i), row0 zeroed -> fp32
    gemm_mma<true, false><<<gg, 256, SMEM_BYTES>>>(
        p_pa, p_wt + OFF_WI, W_i_b, nullptr, p_msg, nullptr, M, KPA, 1);

    bond_bias_kernel<<<M, 128>>>(f_bonds, a2b, Wh0_w + (size_t)DIM * DIM, Wh0_b, p_bias);

    for (int d = 0; d < 4; d++) {
        gather_h<true><<<M, 128>>>(p_msg, a2a, p_pg);
        gemm_mma<true, true><<<gg, 256, SMEM_BYTES>>>(
            p_pg, p_wt + OFF_WH0, nullptr, p_bias, nullptr, p_p0, M, 512, 0);
        gemm_mma<true, true><<<gg, 256, SMEM_BYTES>>>(
            p_p0, p_wt + OFF_WH1, Wh1_b, nullptr, nullptr, p_p1, M, 512, 0);
        gemm_mma<false, false><<<gg, 256, SMEM_BYTES>>>(
            p_p1, p_wt + OFF_WH2, Wh2_b, p_msg, p_msg, nullptr, M, 512, 1);
    }

    // a_message (NO relu) -> fp16
    gather_h<false><<<M, 128>>>(p_msg, a2a, p_pg);

    cudaMemsetAsync(d_out, 0, (size_t)out_size * sizeof(float), 0);

    // out = relu(cc @ Wo_top + a_message @ Wo_bot + b_o)
    gemm_mma<false, false><<<gg, 256, SMEM_BYTES>>>(
        p_pcc, p_wt + OFF_WOT, W_o_b, nullptr, p_f32a, nullptr, M, 512, 0);
    gemm_mma<true, false><<<gg, 256, SMEM_BYTES>>>(
        p_pg, p_wt + OFF_WOB, nullptr, p_f32a, p_f32b, nullptr, M, 512, 0);

    segment_atomic<<<M, 128>>>(p_f32b, mol_ids, (float*)d_out, n_mols);
}

// round 14
// speedup vs baseline: 2.7684x; 1.0251x over previous
#include <cuda_runtime.h>
#include <cuda_fp16.h>
#include <cstdint>
#include <cstddef>

#define DIM 512
#define MAXA 100000
#define KPA 192

// ---------------- scratch (static device globals; no allocation) ----------------
__device__ float g_msg [(size_t)MAXA * DIM];
__device__ float g_f32a[(size_t)MAXA * DIM];
__device__ float g_f32b[(size_t)MAXA * DIM];
__device__ float g_bias[(size_t)MAXA * DIM];
// fp16 activation buffers (single plane)
__device__ __align__(16) __half g_pa [(size_t)MAXA * KPA];
__device__ __align__(16) __half g_pg [(size_t)MAXA * DIM];
__device__ __align__(16) __half g_p0 [(size_t)MAXA * DIM];
__device__ __align__(16) __half g_p1 [(size_t)MAXA * DIM];
__device__ __align__(16) __half g_pcc[(size_t)MAXA * DIM];
// transposed fp16 weights: [512][Kp] single plane per GEMM
__device__ __align__(16) __half g_wt[2031616];

// ---------------- helpers ----------------
__device__ __forceinline__ uint32_t s2u(const void* p) {
    uint32_t a;
    asm("{ .reg .u64 t; cvta.to.shared.u64 t, %1; cvt.u32.u64 %0, t; }" : "=r"(a) : "l"(p));
    return a;
}

#define CP16(dst, src) \
    asm volatile("cp.async.cg.shared.global [%0], [%1], 16;" :: "r"(dst), "l"(src) : "memory")
#define CP_COMMIT() asm volatile("cp.async.commit_group;" ::: "memory")
#define CP_WAIT1()  asm volatile("cp.async.wait_group 1;" ::: "memory")

#define LDSM4(r, addr) \
    asm volatile("ldmatrix.sync.aligned.m8n8.x4.shared.b16 {%0,%1,%2,%3}, [%4];" \
        : "=r"((r)[0]), "=r"((r)[1]), "=r"((r)[2]), "=r"((r)[3]) : "r"(addr))

#define MMA16816(d, a, b0, b1) \
    asm volatile("mma.sync.aligned.m16n8k16.row.col.f32.f16.f16.f32 " \
        "{%0,%1,%2,%3}, {%4,%5,%6,%7}, {%8,%9}, {%0,%1,%2,%3};" \
        : "+f"((d)[0]), "+f"((d)[1]), "+f"((d)[2]), "+f"((d)[3]) \
        : "r"((a)[0]), "r"((a)[1]), "r"((a)[2]), "r"((a)[3]), "r"(b0), "r"(b1))

// ---------------- fused prep: atoms fp16 + all 9 weight transposes ----------------
__global__ void prep_all(const float* __restrict__ fa,
    const float* __restrict__ W_i,  const float* __restrict__ Wah0,
    const float* __restrict__ Wah1, const float* __restrict__ Wah2,
    const float* __restrict__ Wh0,  const float* __restrict__ Wh1,
    const float* __restrict__ Wh2,  const float* __restrict__ Wot,
    const float* __restrict__ Wob,
    __half* __restrict__ wt, __half* __restrict__ pa, int M)
{
    const int tid0 = blockIdx.x * blockDim.x + threadIdx.x;
    const int stride = gridDim.x * blockDim.x;

    for (int idx = tid0; idx < M * KPA; idx += stride) {
        int row = idx / KPA, k = idx - row * KPA;
        float v = (k < 133) ? fa[(size_t)row * 133 + k] : 0.f;
        pa[idx] = __float2half(v);
    }

    const float* srcs[9] = {W_i, Wah0, Wah1, Wah2, Wh0, Wh1, Wh2, Wot, Wob};
    const int    kre[9]  = {133, 133, 512, 512, 512, 512, 512, 512, 512};
    const int    kps[9]  = {KPA, KPA, 512, 512, 512, 512, 512, 512, 512};
    size_t off = 0;
    #pragma unroll 1
    for (int t = 0; t < 9; t++) {
        const int Kp = kps[t], total = 512 * Kp, kr = kre[t];
        const float* W = srcs[t];
        __half* out = wt + off;
        for (int idx = tid0; idx < total; idx += stride) {
            int n = idx / Kp, k = idx - n * Kp;
            float v = (k < kr) ? W[(size_t)k * 512 + n] : 0.f;
            out[idx] = __float2half(v);
        }
        off += total;
    }
}

// ---------------- HMMA GEMM: out = f(A @ W + bias + add), pure fp16 -------------------
// CTA tile 128M x 128N, BK=64, grid (4, ceil(M/128)), 256 threads, warp tile 32x64.
// 3-stage cp.async pipeline, ONE __syncthreads per chunk.
// smem 110592 B (stage 36864: A@0 18432, B@18432), 2 CTAs/SM.
// Rows 144 B (128 data + 16 pad) -> conflict-free ldmatrix.
template<bool RELU_OUT, bool EMIT_H>
__global__ void __launch_bounds__(256, 2) gemm_mma(
    const __half* __restrict__ A,
    const __half* __restrict__ Wp,
    const float* __restrict__ bias, const float* __restrict__ addf,
    float* __restrict__ Cf, __half* __restrict__ Cp,
    int M, int Kp, int zero_row0)
{
    extern __shared__ __align__(16) char smem[];
    const uint32_t sb = s2u(smem);
    const uint32_t RS = 144;
    const uint32_t B_OFF = 18432, STG = 36864;

    const int tid = threadIdx.x, lane = tid & 31, wid = tid >> 5;
    const int wm = wid >> 1, wn = wid & 1;    // warp grid 4x2, warp tile 32M x 64N
    const int row0 = blockIdx.y * 128, col0 = blockIdx.x * 128;
    const int nch = Kp >> 6;

    float acc[2][8][4];
    #pragma unroll
    for (int i = 0; i < 2; i++)
        #pragma unroll
        for (int j = 0; j < 8; j++)
            #pragma unroll
            for (int q = 0; q < 4; q++) acc[i][j][q] = 0.f;

    // loaders: 2 threads/row (128 rows), 32 elems (64 B) each
    const int lr = tid >> 1, seg = (tid & 1) * 32;
    const int agrow = row0 + lr;
    const uint32_t dst = (uint32_t)lr * RS + (uint32_t)seg * 2;

    auto issue = [&](int c, int buf) {
        uint32_t base = sb + (uint32_t)buf * STG;
        if (agrow < M) {
            const __half* s = A + (size_t)agrow * Kp + c * 64 + seg;
            uint32_t d = base + dst;
            CP16(d, s);            CP16(d + 16, s + 8);
            CP16(d + 32, s + 16);  CP16(d + 48, s + 24);
        }
        {
            const __half* s = Wp + (size_t)(col0 + lr) * Kp + c * 64 + seg;
            uint32_t d = base + B_OFF + dst;
            CP16(d, s);            CP16(d + 16, s + 8);
            CP16(d + 32, s + 16);  CP16(d + 48, s + 24);
        }
    };

    // ldmatrix constant offsets
    const uint32_t a_off = (uint32_t)(wm * 32 + (lane & 15)) * RS + (uint32_t)(lane >> 4) * 16;
    const uint32_t b_off = (uint32_t)(wn * 64 + (lane & 7) + ((lane >> 4) & 1) * 8) * RS
                           + (uint32_t)((lane >> 3) & 1) * 16;

    // prologue: stages 0 and 1 in flight
    issue(0, 0);
    CP_COMMIT();
    if (nch > 1) issue(1, 1);
    CP_COMMIT();

    int stage = 0;
    for (int c = 0; c < nch; c++) {
        CP_WAIT1();               // stage c's group retired (<=1 newer pending)
        __syncthreads();          // stage c visible to all; all done reading stage (c-1)%3

        if (c + 2 < nch) issue(c + 2, (c + 2) % 3);   // overwrites stage (c-1)%3: safe
        CP_COMMIT();

        const uint32_t sbase = sb + (uint32_t)stage * STG;
        const uint32_t abase = sbase + a_off;
        const uint32_t bbase = sbase + B_OFF + b_off;
        #pragma unroll
        for (int ks = 0; ks < 4; ks++) {
            uint32_t ah[2][4];
            #pragma unroll
            for (int mt = 0; mt < 2; mt++)
                LDSM4(ah[mt], abase + mt * 16 * RS + ks * 32);
            #pragma unroll
            for (int ntp = 0; ntp < 4; ntp++) {
                uint32_t bh[4];
                LDSM4(bh, bbase + ntp * 16 * RS + ks * 32);
                #pragma unroll
                for (int h = 0; h < 2; h++) {
                    const int nt = ntp * 2 + h;
                    #pragma unroll
                    for (int mt = 0; mt < 2; mt++)
                        MMA16816(acc[mt][nt], ah[mt], bh[2 * h], bh[2 * h + 1]);
                }
            }
        }
        stage = (stage + 1 == 3) ? 0 : stage + 1;
    }

    // ---- epilogue ----
    const int g = lane >> 2, tg = lane & 3;
    #pragma unroll
    for (int mt = 0; mt < 2; mt++) {
        #pragma unroll
        for (int nt = 0; nt < 8; nt++) {
            const int col = col0 + wn * 64 + nt * 8 + tg * 2;
            #pragma unroll
            for (int half = 0; half < 2; half++) {
                const int row = row0 + wm * 32 + mt * 16 + g + half * 8;
                if (row >= M) continue;
                float v0 = acc[mt][nt][half * 2 + 0];
                float v1 = acc[mt][nt][half * 2 + 1];
                if (bias) {
                    const float2 bv = *(const float2*)(bias + col);
                    v0 += bv.x; v1 += bv.y;
                }
                if (addf) {
                    const float2 av = *(const float2*)(addf + (size_t)row * DIM + col);
                    v0 += av.x; v1 += av.y;
                }
                if (RELU_OUT) { v0 = fmaxf(v0, 0.f); v1 = fmaxf(v1, 0.f); }
                if (zero_row0 && row == 0) { v0 = 0.f; v1 = 0.f; }
                if (EMIT_H) {
                    __half2 hp = __floats2half2_rn(v0, v1);
                    *(__half2*)(Cp + (size_t)row * DIM + col) = hp;
                } else {
                    *(float2*)(Cf + (size_t)row * DIM + col) = make_float2(v0, v1);
                }
            }
        }
    }
}

// ---------------- gather-sum + optional relu -> fp16 ----------------
template<bool RELU>
__global__ void gather_h(const float* __restrict__ src, const int* __restrict__ a2a,
                         __half* __restrict__ out)
{
    const int atom = blockIdx.x;
    const int t = threadIdx.x;                 // 128 threads x 4 floats
    const int* idx = a2a + (size_t)atom * 6;
    float4 acc = make_float4(0.f, 0.f, 0.f, 0.f);
    #pragma unroll
    for (int j = 0; j < 6; j++) {
        const float4 v = *(const float4*)(src + (size_t)idx[j] * DIM + t * 4);
        acc.x += v.x; acc.y += v.y; acc.z += v.z; acc.w += v.w;
    }
    if (RELU) {
        acc.x = fmaxf(acc.x, 0.f); acc.y = fmaxf(acc.y, 0.f);
        acc.z = fmaxf(acc.z, 0.f); acc.w = fmaxf(acc.w, 0.f);
    }
    __half2 h0 = __floats2half2_rn(acc.x, acc.y);
    __half2 h1 = __floats2half2_rn(acc.z, acc.w);
    *(__half2*)(out + (size_t)atom * DIM + t * 4)     = h0;
    *(__half2*)(out + (size_t)atom * DIM + t * 4 + 2) = h1;
}

// ---------------- bond bias ----------------
__global__ void bond_bias_kernel(const float* __restrict__ f_bonds, const int* __restrict__ a2b,
                                 const float* __restrict__ Wb, const float* __restrict__ b0,
                                 float* __restrict__ dst)
{
    const int atom = blockIdx.x;
    const int t = threadIdx.x;
    __shared__ float bs[14];
    if (t < 14) {
        const int* idx = a2b + (size_t)atom * 6;
        float s = 0.f;
        #pragma unroll
        for (int j = 0; j < 6; j++) s += f_bonds[(size_t)idx[j] * 14 + t];
        bs[t] = fmaxf(s, 0.f);
    }
    __syncthreads();
    #pragma unroll
    for (int rr = 0; rr < 4; rr++) {
        int n = t + rr * 128;
        float acc = b0[n];
        #pragma unroll
        for (int k = 0; k < 14; k++) acc = fmaf(bs[k], Wb[k * DIM + n], acc);
        dst[(size_t)atom * DIM + n] = acc;
    }
}

// ---------------- segment sum via atomics ----------------
__global__ void segment_atomic(const float* __restrict__ x, const int* __restrict__ mol_ids,
                               float* __restrict__ out, int n_mols)
{
    const int atom = blockIdx.x;
    const int mid = mol_ids[atom];
    if (mid < 0 || mid >= n_mols) return;
    const int t = threadIdx.x;
    #pragma unroll
    for (int rr = 0; rr < 4; rr++) {
        int n = t + rr * 128;
        atomicAdd(out + (size_t)mid * DIM + n, x[(size_t)atom * DIM + n]);
    }
}

extern "C" void kernel_launch(void* const* d_in, const int* in_sizes, int n_in,
                              void* d_out, int out_size)
{
    const float* f_atoms = (const float*)d_in[0];
    const float* f_bonds = (const float*)d_in[1];
    const int*   a2a     = (const int*)d_in[2];
    const int*   a2b     = (const int*)d_in[3];
    const int*   mol_ids = (const int*)d_in[4];
    const int base = n_in - 16;
    const float* W_i_w  = (const float*)d_in[base + 0];
    const float* W_i_b  = (const float*)d_in[base + 1];
    const float* Wh0_w  = (const float*)d_in[base + 2];
    const float* Wh0_b  = (const float*)d_in[base + 3];
    const float* Wh1_w  = (const float*)d_in[base + 4];
    const float* Wh1_b  = (const float*)d_in[base + 5];
    const float* Wh2_w  = (const float*)d_in[base + 6];
    const float* Wh2_b  = (const float*)d_in[base + 7];
    const float* Wah0_w = (const float*)d_in[base + 8];
    const float* Wah0_b = (const float*)d_in[base + 9];
    const float* Wah1_w = (const float*)d_in[base + 10];
    const float* Wah1_b = (const float*)d_in[base + 11];
    const float* Wah2_w = (const float*)d_in[base + 12];
    const float* Wah2_b = (const float*)d_in[base + 13];
    const float* W_o_w  = (const float*)d_in[base + 14];
    const float* W_o_b  = (const float*)d_in[base + 15];

    const int M      = in_sizes[0] / 133;
    const int n_mols = out_size / DIM;

    float *p_msg, *p_f32a, *p_f32b, *p_bias;
    __half *p_pa, *p_pg, *p_p0, *p_p1, *p_pcc, *p_wt;
    cudaGetSymbolAddress((void**)&p_msg,  g_msg);
    cudaGetSymbolAddress((void**)&p_f32a, g_f32a);
    cudaGetSymbolAddress((void**)&p_f32b, g_f32b);
    cudaGetSymbolAddress((void**)&p_bias, g_bias);
    cudaGetSymbolAddress((void**)&p_pa,   g_pa);
    cudaGetSymbolAddress((void**)&p_pg,   g_pg);
    cudaGetSymbolAddress((void**)&p_p0,   g_p0);
    cudaGetSymbolAddress((void**)&p_p1,   g_p1);
    cudaGetSymbolAddress((void**)&p_pcc,  g_pcc);
    cudaGetSymbolAddress((void**)&p_wt,   g_wt);

    // weight offsets in fp16 elements — matches prep_all order
    const size_t OFF_WI   = 0;
    const size_t OFF_WAH0 = 98304;
    const size_t OFF_WAH1 = 196608;
    const size_t OFF_WAH2 = 458752;
    const size_t OFF_WH0  = 720896;
    const size_t OFF_WH1  = 983040;
    const size_t OFF_WH2  = 1245184;
    const size_t OFF_WOT  = 1507328;
    const size_t OFF_WOB  = 1769472;

    const int SMEM_BYTES = 110592;
    cudaFuncSetAttribute(gemm_mma<true,  true >, cudaFuncAttributeMaxDynamicSharedMemorySize, SMEM_BYTES);
    cudaFuncSetAttribute(gemm_mma<true,  false>, cudaFuncAttributeMaxDynamicSharedMemorySize, SMEM_BYTES);
    cudaFuncSetAttribute(gemm_mma<false, false>, cudaFuncAttributeMaxDynamicSharedMemorySize, SMEM_BYTES);

    const dim3 gg(4, (M + 127) / 128);

    // launch 0: ALL prep fused
    prep_all<<<1024, 256>>>(f_atoms, W_i_w, Wah0_w, Wah1_w, Wah2_w,
                            Wh0_w, Wh1_w, Wh2_w, W_o_w, W_o_w + (size_t)DIM * DIM,
                            p_wt, p_pa, M);

    // launches 1-3: cc chain (GEMMs — ncu capture lands here)
    gemm_mma<true, true><<<gg, 256, SMEM_BYTES>>>(
        p_pa, p_wt + OFF_WAH0, Wah0_b, nullptr, nullptr, p_p0, M, KPA, 0);
    gemm_mma<true, true><<<gg, 256, SMEM_BYTES>>>(
        p_p0, p_wt + OFF_WAH1, Wah1_b, nullptr, nullptr, p_p1, M, 512, 0);
    gemm_mma<true, true><<<gg, 256, SMEM_BYTES>>>(
        p_p1, p_wt + OFF_WAH2, Wah2_b, nullptr, nullptr, p_pcc, M, 512, 0);

    // msg = relu(f_atoms @ W_i + b_i), row0 zeroed -> fp32
    gemm_mma<true, false><<<gg, 256, SMEM_BYTES>>>(
        p_pa, p_wt + OFF_WI, W_i_b, nullptr, p_msg, nullptr, M, KPA, 1);

    bond_bias_kernel<<<M, 128>>>(f_bonds, a2b, Wh0_w + (size_t)DIM * DIM, Wh0_b, p_bias);

    for (int d = 0; d < 4; d++) {
        gather_h<true><<<M, 128>>>(p_msg, a2a, p_pg);
        gemm_mma<true, true><<<gg, 256, SMEM_BYTES>>>(
            p_pg, p_wt + OFF_WH0, nullptr, p_bias, nullptr, p_p0, M, 512, 0);
        gemm_mma<true, true><<<gg, 256, SMEM_BYTES>>>(
            p_p0, p_wt + OFF_WH1, Wh1_b, nullptr, nullptr, p_p1, M, 512, 0);
        gemm_mma<false, false><<<gg, 256, SMEM_BYTES>>>(
            p_p1, p_wt + OFF_WH2, Wh2_b, p_msg, p_msg, nullptr, M, 512, 1);
    }

    // a_message (NO relu) -> fp16
    gather_h<false><<<M, 128>>>(p_msg, a2a, p_pg);

    cudaMemsetAsync(d_out, 0, (size_t)out_size * sizeof(float), 0);

    // out = relu(cc @ Wo_top + a_message @ Wo_bot + b_o)
    gemm_mma<false, false><<<gg, 256, SMEM_BYTES>>>(
        p_pcc, p_wt + OFF_WOT, W_o_b, nullptr, p_f32a, nullptr, M, 512, 0);
    gemm_mma<true, false><<<gg, 256, SMEM_BYTES>>>(
        p_pg, p_wt + OFF_WOB, nullptr, p_f32a, p_f32b, nullptr, M, 512, 0);

    segment_atomic<<<M, 128>>>(p_f32b, mol_ids, (float*)d_out, n_mols);
}

// round 15
// speedup vs baseline: 2.8335x; 1.0235x over previous
#include <cuda_runtime.h>
#include <cuda_fp16.h>
#include <cstdint>
#include <cstddef>

#define DIM 512
#define MAXA 100000
#define KPA 192

// ---------------- scratch (static device globals; no allocation) ----------------
__device__ float g_msg [(size_t)MAXA * DIM];
__device__ float g_f32a[(size_t)MAXA * DIM];
__device__ float g_f32b[(size_t)MAXA * DIM];
__device__ float g_bias[(size_t)MAXA * DIM];
// fp16 activation buffers (single plane)
__device__ __align__(16) __half g_pa  [(size_t)MAXA * KPA];
__device__ __align__(16) __half g_msgh[(size_t)MAXA * DIM];   // fp16 mirror of msg
__device__ __align__(16) __half g_pg  [(size_t)MAXA * DIM];
__device__ __align__(16) __half g_p0  [(size_t)MAXA * DIM];
__device__ __align__(16) __half g_p1  [(size_t)MAXA * DIM];
__device__ __align__(16) __half g_pcc [(size_t)MAXA * DIM];
// transposed fp16 weights: [512][Kp] single plane per GEMM
__device__ __align__(16) __half g_wt[2031616];

// ---------------- helpers ----------------
__device__ __forceinline__ uint32_t s2u(const void* p) {
    uint32_t a;
    asm("{ .reg .u64 t; cvta.to.shared.u64 t, %1; cvt.u32.u64 %0, t; }" : "=r"(a) : "l"(p));
    return a;
}

#define CP16(dst, src) \
    asm volatile("cp.async.cg.shared.global [%0], [%1], 16;" :: "r"(dst), "l"(src) : "memory")
#define CP_COMMIT() asm volatile("cp.async.commit_group;" ::: "memory")
#define CP_WAIT1()  asm volatile("cp.async.wait_group 1;" ::: "memory")

#define LDSM4(r, addr) \
    asm volatile("ldmatrix.sync.aligned.m8n8.x4.shared.b16 {%0,%1,%2,%3}, [%4];" \
        : "=r"((r)[0]), "=r"((r)[1]), "=r"((r)[2]), "=r"((r)[3]) : "r"(addr))

#define MMA16816(d, a, b0, b1) \
    asm volatile("mma.sync.aligned.m16n8k16.row.col.f32.f16.f16.f32 " \
        "{%0,%1,%2,%3}, {%4,%5,%6,%7}, {%8,%9}, {%0,%1,%2,%3};" \
        : "+f"((d)[0]), "+f"((d)[1]), "+f"((d)[2]), "+f"((d)[3]) \
        : "r"((a)[0]), "r"((a)[1]), "r"((a)[2]), "r"((a)[3]), "r"(b0), "r"(b1))

// ---------------- fused prep: atoms fp16 + all 9 weight transposes ----------------
__global__ void prep_all(const float* __restrict__ fa,
    const float* __restrict__ W_i,  const float* __restrict__ Wah0,
    const float* __restrict__ Wah1, const float* __restrict__ Wah2,
    const float* __restrict__ Wh0,  const float* __restrict__ Wh1,
    const float* __restrict__ Wh2,  const float* __restrict__ Wot,
    const float* __restrict__ Wob,
    __half* __restrict__ wt, __half* __restrict__ pa, int M)
{
    const int tid0 = blockIdx.x * blockDim.x + threadIdx.x;
    const int stride = gridDim.x * blockDim.x;

    for (int idx = tid0; idx < M * KPA; idx += stride) {
        int row = idx / KPA, k = idx - row * KPA;
        float v = (k < 133) ? fa[(size_t)row * 133 + k] : 0.f;
        pa[idx] = __float2half(v);
    }

    const float* srcs[9] = {W_i, Wah0, Wah1, Wah2, Wh0, Wh1, Wh2, Wot, Wob};
    const int    kre[9]  = {133, 133, 512, 512, 512, 512, 512, 512, 512};
    const int    kps[9]  = {KPA, KPA, 512, 512, 512, 512, 512, 512, 512};
    size_t off = 0;
    #pragma unroll 1
    for (int t = 0; t < 9; t++) {
        const int Kp = kps[t], total = 512 * Kp, kr = kre[t];
        const float* W = srcs[t];
        __half* out = wt + off;
        for (int idx = tid0; idx < total; idx += stride) {
            int n = idx / Kp, k = idx - n * Kp;
            float v = (k < kr) ? W[(size_t)k * 512 + n] : 0.f;
            out[idx] = __float2half(v);
        }
        off += total;
    }
}

// ---------------- HMMA GEMM: out = f(A @ W + bias + add), pure fp16 -------------------
// CTA tile 128M x 128N, BK=64, grid (4, ceil(M/128)), 256 threads, warp tile 32x64.
// 3-stage cp.async pipeline, ONE __syncthreads per chunk. smem 110592 B, 2 CTAs/SM.
template<bool RELU_OUT, bool EMIT_H, bool EMIT_F>
__global__ void __launch_bounds__(256, 2) gemm_mma(
    const __half* __restrict__ A,
    const __half* __restrict__ Wp,
    const float* __restrict__ bias, const float* __restrict__ addf,
    float* __restrict__ Cf, __half* __restrict__ Cp,
    int M, int Kp, int zero_row0)
{
    extern __shared__ __align__(16) char smem[];
    const uint32_t sb = s2u(smem);
    const uint32_t RS = 144;
    const uint32_t B_OFF = 18432, STG = 36864;

    const int tid = threadIdx.x, lane = tid & 31, wid = tid >> 5;
    const int wm = wid >> 1, wn = wid & 1;    // warp grid 4x2, warp tile 32M x 64N
    const int row0 = blockIdx.y * 128, col0 = blockIdx.x * 128;
    const int nch = Kp >> 6;

    float acc[2][8][4];
    #pragma unroll
    for (int i = 0; i < 2; i++)
        #pragma unroll
        for (int j = 0; j < 8; j++)
            #pragma unroll
            for (int q = 0; q < 4; q++) acc[i][j][q] = 0.f;

    const int lr = tid >> 1, seg = (tid & 1) * 32;
    const int agrow = row0 + lr;
    const uint32_t dst = (uint32_t)lr * RS + (uint32_t)seg * 2;

    auto issue = [&](int c, int buf) {
        uint32_t base = sb + (uint32_t)buf * STG;
        if (agrow < M) {
            const __half* s = A + (size_t)agrow * Kp + c * 64 + seg;
            uint32_t d = base + dst;
            CP16(d, s);            CP16(d + 16, s + 8);
            CP16(d + 32, s + 16);  CP16(d + 48, s + 24);
        }
        {
            const __half* s = Wp + (size_t)(col0 + lr) * Kp + c * 64 + seg;
            uint32_t d = base + B_OFF + dst;
            CP16(d, s);            CP16(d + 16, s + 8);
            CP16(d + 32, s + 16);  CP16(d + 48, s + 24);
        }
    };

    const uint32_t a_off = (uint32_t)(wm * 32 + (lane & 15)) * RS + (uint32_t)(lane >> 4) * 16;
    const uint32_t b_off = (uint32_t)(wn * 64 + (lane & 7) + ((lane >> 4) & 1) * 8) * RS
                           + (uint32_t)((lane >> 3) & 1) * 16;

    issue(0, 0);
    CP_COMMIT();
    if (nch > 1) issue(1, 1);
    CP_COMMIT();

    int stage = 0;
    for (int c = 0; c < nch; c++) {
        CP_WAIT1();
        __syncthreads();

        if (c + 2 < nch) issue(c + 2, (c + 2) % 3);
        CP_COMMIT();

        const uint32_t sbase = sb + (uint32_t)stage * STG;
        const uint32_t abase = sbase + a_off;
        const uint32_t bbase = sbase + B_OFF + b_off;
        #pragma unroll
        for (int ks = 0; ks < 4; ks++) {
            uint32_t ah[2][4];
            #pragma unroll
            for (int mt = 0; mt < 2; mt++)
                LDSM4(ah[mt], abase + mt * 16 * RS + ks * 32);
            #pragma unroll
            for (int ntp = 0; ntp < 4; ntp++) {
                uint32_t bh[4];
                LDSM4(bh, bbase + ntp * 16 * RS + ks * 32);
                #pragma unroll
                for (int h = 0; h < 2; h++) {
                    const int nt = ntp * 2 + h;
                    #pragma unroll
                    for (int mt = 0; mt < 2; mt++)
                        MMA16816(acc[mt][nt], ah[mt], bh[2 * h], bh[2 * h + 1]);
                }
            }
        }
        stage = (stage + 1 == 3) ? 0 : stage + 1;
    }

    // ---- epilogue ----
    const int g = lane >> 2, tg = lane & 3;
    #pragma unroll
    for (int mt = 0; mt < 2; mt++) {
        #pragma unroll
        for (int nt = 0; nt < 8; nt++) {
            const int col = col0 + wn * 64 + nt * 8 + tg * 2;
            #pragma unroll
            for (int half = 0; half < 2; half++) {
                const int row = row0 + wm * 32 + mt * 16 + g + half * 8;
                if (row >= M) continue;
                float v0 = acc[mt][nt][half * 2 + 0];
                float v1 = acc[mt][nt][half * 2 + 1];
                if (bias) {
                    const float2 bv = *(const float2*)(bias + col);
                    v0 += bv.x; v1 += bv.y;
                }
                if (addf) {
                    const float2 av = *(const float2*)(addf + (size_t)row * DIM + col);
                    v0 += av.x; v1 += av.y;
                }
                if (RELU_OUT) { v0 = fmaxf(v0, 0.f); v1 = fmaxf(v1, 0.f); }
                if (zero_row0 && row == 0) { v0 = 0.f; v1 = 0.f; }
                if (EMIT_F)
                    *(float2*)(Cf + (size_t)row * DIM + col) = make_float2(v0, v1);
                if (EMIT_H)
                    *(__half2*)(Cp + (size_t)row * DIM + col) = __floats2half2_rn(v0, v1);
            }
        }
    }
}

// ---------------- gather-sum (fp16 src) + optional relu -> fp16 ----------------
template<bool RELU>
__global__ void gather_h(const __half* __restrict__ src, const int* __restrict__ a2a,
                         __half* __restrict__ out)
{
    const int atom = blockIdx.x;
    const int t = threadIdx.x;                 // 128 threads x 4 halves
    const int* idx = a2a + (size_t)atom * 6;
    float acc0 = 0.f, acc1 = 0.f, acc2 = 0.f, acc3 = 0.f;
    #pragma unroll
    for (int j = 0; j < 6; j++) {
        const uint2 raw = *(const uint2*)(src + (size_t)idx[j] * DIM + t * 4);
        const float2 v0 = __half22float2(*(const __half2*)&raw.x);
        const float2 v1 = __half22float2(*(const __half2*)&raw.y);
        acc0 += v0.x; acc1 += v0.y; acc2 += v1.x; acc3 += v1.y;
    }
    if (RELU) {
        acc0 = fmaxf(acc0, 0.f); acc1 = fmaxf(acc1, 0.f);
        acc2 = fmaxf(acc2, 0.f); acc3 = fmaxf(acc3, 0.f);
    }
    uint2 packed;
    *(__half2*)&packed.x = __floats2half2_rn(acc0, acc1);
    *(__half2*)&packed.y = __floats2half2_rn(acc2, acc3);
    *(uint2*)(out + (size_t)atom * DIM + t * 4) = packed;
}

// ---------------- bond bias ----------------
__global__ void bond_bias_kernel(const float* __restrict__ f_bonds, const int* __restrict__ a2b,
                                 const float* __restrict__ Wb, const float* __restrict__ b0,
                                 float* __restrict__ dst)
{
    const int atom = blockIdx.x;
    const int t = threadIdx.x;
    __shared__ float bs[14];
    if (t < 14) {
        const int* idx = a2b + (size_t)atom * 6;
        float s = 0.f;
        #pragma unroll
        for (int j = 0; j < 6; j++) s += f_bonds[(size_t)idx[j] * 14 + t];
        bs[t] = fmaxf(s, 0.f);
    }
    __syncthreads();
    #pragma unroll
    for (int rr = 0; rr < 4; rr++) {
        int n = t + rr * 128;
        float acc = b0[n];
        #pragma unroll
        for (int k = 0; k < 14; k++) acc = fmaf(bs[k], Wb[k * DIM + n], acc);
        dst[(size_t)atom * DIM + n] = acc;
    }
}

// ---------------- segment sum via atomics ----------------
__global__ void segment_atomic(const float* __restrict__ x, const int* __restrict__ mol_ids,
                               float* __restrict__ out, int n_mols)
{
    const int atom = blockIdx.x;
    const int mid = mol_ids[atom];
    if (mid < 0 || mid >= n_mols) return;
    const int t = threadIdx.x;
    #pragma unroll
    for (int rr = 0; rr < 4; rr++) {
        int n = t + rr * 128;
        atomicAdd(out + (size_t)mid * DIM + n, x[(size_t)atom * DIM + n]);
    }
}

extern "C" void kernel_launch(void* const* d_in, const int* in_sizes, int n_in,
                              void* d_out, int out_size)
{
    const float* f_atoms = (const float*)d_in[0];
    const float* f_bonds = (const float*)d_in[1];
    const int*   a2a     = (const int*)d_in[2];
    const int*   a2b     = (const int*)d_in[3];
    const int*   mol_ids = (const int*)d_in[4];
    const int base = n_in - 16;
    const float* W_i_w  = (const float*)d_in[base + 0];
    const float* W_i_b  = (const float*)d_in[base + 1];
    const float* Wh0_w  = (const float*)d_in[base + 2];
    const float* Wh0_b  = (const float*)d_in[base + 3];
    const float* Wh1_w  = (const float*)d_in[base + 4];
    const float* Wh1_b  = (const float*)d_in[base + 5];
    const float* Wh2_w  = (const float*)d_in[base + 6];
    const float* Wh2_b  = (const float*)d_in[base + 7];
    const float* Wah0_w = (const float*)d_in[base + 8];
    const float* Wah0_b = (const float*)d_in[base + 9];
    const float* Wah1_w = (const float*)d_in[base + 10];
    const float* Wah1_b = (const float*)d_in[base + 11];
    const float* Wah2_w = (const float*)d_in[base + 12];
    const float* Wah2_b = (const float*)d_in[base + 13];
    const float* W_o_w  = (const float*)d_in[base + 14];
    const float* W_o_b  = (const float*)d_in[base + 15];

    const int M      = in_sizes[0] / 133;
    const int n_mols = out_size / DIM;

    float *p_msg, *p_f32a, *p_f32b, *p_bias;
    __half *p_pa, *p_msgh, *p_pg, *p_p0, *p_p1, *p_pcc, *p_wt;
    cudaGetSymbolAddress((void**)&p_msg,  g_msg);
    cudaGetSymbolAddress((void**)&p_f32a, g_f32a);
    cudaGetSymbolAddress((void**)&p_f32b, g_f32b);
    cudaGetSymbolAddress((void**)&p_bias, g_bias);
    cudaGetSymbolAddress((void**)&p_pa,   g_pa);
    cudaGetSymbolAddress((void**)&p_msgh, g_msgh);
    cudaGetSymbolAddress((void**)&p_pg,   g_pg);
    cudaGetSymbolAddress((void**)&p_p0,   g_p0);
    cudaGetSymbolAddress((void**)&p_p1,   g_p1);
    cudaGetSymbolAddress((void**)&p_pcc,  g_pcc);
    cudaGetSymbolAddress((void**)&p_wt,   g_wt);

    // weight offsets in fp16 elements — matches prep_all order
    const size_t OFF_WI   = 0;
    const size_t OFF_WAH0 = 98304;
    const size_t OFF_WAH1 = 196608;
    const size_t OFF_WAH2 = 458752;
    const size_t OFF_WH0  = 720896;
    const size_t OFF_WH1  = 983040;
    const size_t OFF_WH2  = 1245184;
    const size_t OFF_WOT  = 1507328;
    const size_t OFF_WOB  = 1769472;

    const int SMEM_BYTES = 110592;
    cudaFuncSetAttribute(gemm_mma<true,  true,  false>, cudaFuncAttributeMaxDynamicSharedMemorySize, SMEM_BYTES);
    cudaFuncSetAttribute(gemm_mma<true,  true,  true >, cudaFuncAttributeMaxDynamicSharedMemorySize, SMEM_BYTES);
    cudaFuncSetAttribute(gemm_mma<false, true,  true >, cudaFuncAttributeMaxDynamicSharedMemorySize, SMEM_BYTES);
    cudaFuncSetAttribute(gemm_mma<false, false, true >, cudaFuncAttributeMaxDynamicSharedMemorySize, SMEM_BYTES);
    cudaFuncSetAttribute(gemm_mma<true,  false, true >, cudaFuncAttributeMaxDynamicSharedMemorySize, SMEM_BYTES);

    const dim3 gg(4, (M + 127) / 128);

    // launch 0: ALL prep fused
    prep_all<<<1024, 256>>>(f_atoms, W_i_w, Wah0_w, Wah1_w, Wah2_w,
                            Wh0_w, Wh1_w, Wh2_w, W_o_w, W_o_w + (size_t)DIM * DIM,
                            p_wt, p_pa, M);

    // launches 1-3: cc chain (GEMMs — ncu capture lands here)
    gemm_mma<true, true, false><<<gg, 256, SMEM_BYTES>>>(
        p_pa, p_wt + OFF_WAH0, Wah0_b, nullptr, nullptr, p_p0, M, KPA, 0);
    gemm_mma<true, true, false><<<gg, 256, SMEM_BYTES>>>(
        p_p0, p_wt + OFF_WAH1, Wah1_b, nullptr, nullptr, p_p1, M, 512, 0);
    gemm_mma<true, true, false><<<gg, 256, SMEM_BYTES>>>(
        p_p1, p_wt + OFF_WAH2, Wah2_b, nullptr, nullptr, p_pcc, M, 512, 0);

    // msg = relu(f_atoms @ W_i + b_i), row0 zeroed -> fp32 + fp16 mirror
    gemm_mma<true, true, true><<<gg, 256, SMEM_BYTES>>>(
        p_pa, p_wt + OFF_WI, W_i_b, nullptr, p_msg, p_msgh, M, KPA, 1);

    bond_bias_kernel<<<M, 128>>>(f_bonds, a2b, Wh0_w + (size_t)DIM * DIM, Wh0_b, p_bias);

    for (int d = 0; d < 4; d++) {
        gather_h<true><<<M, 128>>>(p_msgh, a2a, p_pg);
        gemm_mma<true, true, false><<<gg, 256, SMEM_BYTES>>>(
            p_pg, p_wt + OFF_WH0, nullptr, p_bias, nullptr, p_p0, M, 512, 0);
        gemm_mma<true, true, false><<<gg, 256, SMEM_BYTES>>>(
            p_p0, p_wt + OFF_WH1, Wh1_b, nullptr, nullptr, p_p1, M, 512, 0);
        // msg = t1 @ Wh2 + b2 + msg (fp32 residual + fp16 mirror, row0 zeroed)
        gemm_mma<false, true, true><<<gg, 256, SMEM_BYTES>>>(
            p_p1, p_wt + OFF_WH2, Wh2_b, p_msg, p_msg, p_msgh, M, 512, 1);
    }

    // a_message (NO relu) -> fp16
    gather_h<false><<<M, 128>>>(p_msgh, a2a, p_pg);

    cudaMemsetAsync(d_out, 0, (size_t)out_size * sizeof(float), 0);

    // out = relu(cc @ Wo_top + a_message @ Wo_bot + b_o)
    gemm_mma<false, false, true><<<gg, 256, SMEM_BYTES>>>(
        p_pcc, p_wt + OFF_WOT, W_o_b, nullptr, p_f32a, nullptr, M, 512, 0);
    gemm_mma<true, false, true><<<gg, 256, SMEM_BYTES>>>(
        p_pg, p_wt + OFF_WOB, nullptr, p_f32a, p_f32b, nullptr, M, 512, 0);

    segment_atomic<<<M, 128>>>(p_f32b, mol_ids, (float*)d_out, n_mols);
}

// round 16
// speedup vs baseline: 2.8695x; 1.0127x over previous
#include <cuda_runtime.h>
#include <cuda_fp16.h>
#include <cstdint>
#include <cstddef>

#define DIM 512
#define MAXA 100000
#define KPA 192

// ---------------- scratch (static device globals; no allocation) ----------------
__device__ float g_msg [(size_t)MAXA * DIM];
__device__ float g_f32b[(size_t)MAXA * DIM];
// fp16 buffers
__device__ __align__(16) __half g_biash[(size_t)MAXA * DIM];
__device__ __align__(16) __half g_pa  [(size_t)MAXA * KPA];
__device__ __align__(16) __half g_msgh[(size_t)MAXA * DIM];   // fp16 mirror of msg
__device__ __align__(16) __half g_pg  [(size_t)MAXA * DIM];
__device__ __align__(16) __half g_p0  [(size_t)MAXA * DIM];
__device__ __align__(16) __half g_p1  [(size_t)MAXA * DIM];
__device__ __align__(16) __half g_pcc [(size_t)MAXA * DIM];
// transposed fp16 weights
__device__ __align__(16) __half g_wt[2031616];

// ---------------- helpers ----------------
__device__ __forceinline__ uint32_t s2u(const void* p) {
    uint32_t a;
    asm("{ .reg .u64 t; cvta.to.shared.u64 t, %1; cvt.u32.u64 %0, t; }" : "=r"(a) : "l"(p));
    return a;
}

#define CP16(dst, src) \
    asm volatile("cp.async.cg.shared.global [%0], [%1], 16;" :: "r"(dst), "l"(src) : "memory")
#define CP_COMMIT() asm volatile("cp.async.commit_group;" ::: "memory")
#define CP_WAIT1()  asm volatile("cp.async.wait_group 1;" ::: "memory")

#define LDSM4(r, addr) \
    asm volatile("ldmatrix.sync.aligned.m8n8.x4.shared.b16 {%0,%1,%2,%3}, [%4];" \
        : "=r"((r)[0]), "=r"((r)[1]), "=r"((r)[2]), "=r"((r)[3]) : "r"(addr))

#define MMA16816(d, a, b0, b1) \
    asm volatile("mma.sync.aligned.m16n8k16.row.col.f32.f16.f16.f32 " \
        "{%0,%1,%2,%3}, {%4,%5,%6,%7}, {%8,%9}, {%0,%1,%2,%3};" \
        : "+f"((d)[0]), "+f"((d)[1]), "+f"((d)[2]), "+f"((d)[3]) \
        : "r"((a)[0]), "r"((a)[1]), "r"((a)[2]), "r"((a)[3]), "r"(b0), "r"(b1))

// ---------------- fused prep: atoms fp16 + all weight transposes ----------------
// order/offsets: WI(192), WAH0(192), WAH1(512), WAH2(512), WH0(512), WH1(512),
//                WH2(512), WO(1024 = full W_o_w)
__global__ void prep_all(const float* __restrict__ fa,
    const float* __restrict__ W_i,  const float* __restrict__ Wah0,
    const float* __restrict__ Wah1, const float* __restrict__ Wah2,
    const float* __restrict__ Wh0,  const float* __restrict__ Wh1,
    const float* __restrict__ Wh2,  const float* __restrict__ Wo,
    __half* __restrict__ wt, __half* __restrict__ pa, int M)
{
    const int tid0 = blockIdx.x * blockDim.x + threadIdx.x;
    const int stride = gridDim.x * blockDim.x;

    for (int idx = tid0; idx < M * KPA; idx += stride) {
        int row = idx / KPA, k = idx - row * KPA;
        float v = (k < 133) ? fa[(size_t)row * 133 + k] : 0.f;
        pa[idx] = __float2half(v);
    }

    const float* srcs[8] = {W_i, Wah0, Wah1, Wah2, Wh0, Wh1, Wh2, Wo};
    const int    kre[8]  = {133, 133, 512, 512, 512, 512, 512, 1024};
    const int    kps[8]  = {KPA, KPA, 512, 512, 512, 512, 512, 1024};
    size_t off = 0;
    #pragma unroll 1
    for (int t = 0; t < 8; t++) {
        const int Kp = kps[t], total = 512 * Kp, kr = kps[t] == 1024 ? 1024 : kre[t];
        const float* W = srcs[t];
        __half* out = wt + off;
        for (int idx = tid0; idx < total; idx += stride) {
            int n = idx / Kp, k = idx - n * Kp;
            float v = (k < kr) ? W[(size_t)k * 512 + n] : 0.f;
            out[idx] = __float2half(v);
        }
        off += total;
    }
}

// ---------------- HMMA GEMM: out = f([A|A2] @ W + bias + addf + addh), pure fp16 ------
// CTA tile 128M x 128N, BK=64, grid (4, ceil(M/128)), 256 threads, warp tile 32x64.
// 3-stage cp.async pipeline, ONE __syncthreads per chunk. smem 110592 B, 2 CTAs/SM.
// A chunks c < nchA come from A (row stride KpA); c >= nchA from A2 (same stride).
template<bool RELU_OUT, bool EMIT_H, bool EMIT_F>
__global__ void __launch_bounds__(256, 2) gemm_mma(
    const __half* __restrict__ A, const __half* __restrict__ A2, int nchA, int KpA,
    const __half* __restrict__ Wp,
    const float* __restrict__ bias,
    const float* __restrict__ addf, const __half* __restrict__ addh,
    float* __restrict__ Cf, __half* __restrict__ Cp,
    int M, int Kp, int zero_row0)
{
    extern __shared__ __align__(16) char smem[];
    const uint32_t sb = s2u(smem);
    const uint32_t RS = 144;
    const uint32_t B_OFF = 18432, STG = 36864;

    const int tid = threadIdx.x, lane = tid & 31, wid = tid >> 5;
    const int wm = wid >> 1, wn = wid & 1;    // warp grid 4x2, warp tile 32M x 64N
    const int row0 = blockIdx.y * 128, col0 = blockIdx.x * 128;
    const int nch = Kp >> 6;

    float acc[2][8][4];
    #pragma unroll
    for (int i = 0; i < 2; i++)
        #pragma unroll
        for (int j = 0; j < 8; j++)
            #pragma unroll
            for (int q = 0; q < 4; q++) acc[i][j][q] = 0.f;

    const int lr = tid >> 1, seg = (tid & 1) * 32;
    const int agrow = row0 + lr;
    const uint32_t dst = (uint32_t)lr * RS + (uint32_t)seg * 2;

    auto issue = [&](int c, int buf) {
        uint32_t base = sb + (uint32_t)buf * STG;
        if (agrow < M) {
            const __half* As = (c < nchA) ? A : A2;
            const int cc = (c < nchA) ? c : c - nchA;
            const __half* s = As + (size_t)agrow * KpA + cc * 64 + seg;
            uint32_t d = base + dst;
            CP16(d, s);            CP16(d + 16, s + 8);
            CP16(d + 32, s + 16);  CP16(d + 48, s + 24);
        }
        {
            const __half* s = Wp + (size_t)(col0 + lr) * Kp + c * 64 + seg;
            uint32_t d = base + B_OFF + dst;
            CP16(d, s);            CP16(d + 16, s + 8);
            CP16(d + 32, s + 16);  CP16(d + 48, s + 24);
        }
    };

    const uint32_t a_off = (uint32_t)(wm * 32 + (lane & 15)) * RS + (uint32_t)(lane >> 4) * 16;
    const uint32_t b_off = (uint32_t)(wn * 64 + (lane & 7) + ((lane >> 4) & 1) * 8) * RS
                           + (uint32_t)((lane >> 3) & 1) * 16;

    issue(0, 0);
    CP_COMMIT();
    if (nch > 1) issue(1, 1);
    CP_COMMIT();

    int stage = 0;
    for (int c = 0; c < nch; c++) {
        CP_WAIT1();
        __syncthreads();

        if (c + 2 < nch) issue(c + 2, (c + 2) % 3);
        CP_COMMIT();

        const uint32_t sbase = sb + (uint32_t)stage * STG;
        const uint32_t abase = sbase + a_off;
        const uint32_t bbase = sbase + B_OFF + b_off;
        #pragma unroll
        for (int ks = 0; ks < 4; ks++) {
            uint32_t ah[2][4];
            #pragma unroll
            for (int mt = 0; mt < 2; mt++)
                LDSM4(ah[mt], abase + mt * 16 * RS + ks * 32);
            #pragma unroll
            for (int ntp = 0; ntp < 4; ntp++) {
                uint32_t bh[4];
                LDSM4(bh, bbase + ntp * 16 * RS + ks * 32);
                #pragma unroll
                for (int h = 0; h < 2; h++) {
                    const int nt = ntp * 2 + h;
                    #pragma unroll
                    for (int mt = 0; mt < 2; mt++)
                        MMA16816(acc[mt][nt], ah[mt], bh[2 * h], bh[2 * h + 1]);
                }
            }
        }
        stage = (stage + 1 == 3) ? 0 : stage + 1;
    }

    // ---- epilogue ----
    const int g = lane >> 2, tg = lane & 3;
    #pragma unroll
    for (int mt = 0; mt < 2; mt++) {
        #pragma unroll
        for (int nt = 0; nt < 8; nt++) {
            const int col = col0 + wn * 64 + nt * 8 + tg * 2;
            #pragma unroll
            for (int half = 0; half < 2; half++) {
                const int row = row0 + wm * 32 + mt * 16 + g + half * 8;
                if (row >= M) continue;
                float v0 = acc[mt][nt][half * 2 + 0];
                float v1 = acc[mt][nt][half * 2 + 1];
                if (bias) {
                    const float2 bv = *(const float2*)(bias + col);
                    v0 += bv.x; v1 += bv.y;
                }
                if (addf) {
                    const float2 av = *(const float2*)(addf + (size_t)row * DIM + col);
                    v0 += av.x; v1 += av.y;
                }
                if (addh) {
                    const float2 av = __half22float2(*(const __half2*)(addh + (size_t)row * DIM + col));
                    v0 += av.x; v1 += av.y;
                }
                if (RELU_OUT) { v0 = fmaxf(v0, 0.f); v1 = fmaxf(v1, 0.f); }
                if (zero_row0 && row == 0) { v0 = 0.f; v1 = 0.f; }
                if (EMIT_F)
                    *(float2*)(Cf + (size_t)row * DIM + col) = make_float2(v0, v1);
                if (EMIT_H)
                    *(__half2*)(Cp + (size_t)row * DIM + col) = __floats2half2_rn(v0, v1);
            }
        }
    }
}

// ---------------- gather-sum (fp16 src) + optional relu -> fp16 ----------------
template<bool RELU>
__global__ void gather_h(const __half* __restrict__ src, const int* __restrict__ a2a,
                         __half* __restrict__ out)
{
    const int atom = blockIdx.x;
    const int t = threadIdx.x;                 // 128 threads x 4 halves
    const int* idx = a2a + (size_t)atom * 6;
    float acc0 = 0.f, acc1 = 0.f, acc2 = 0.f, acc3 = 0.f;
    #pragma unroll
    for (int j = 0; j < 6; j++) {
        const uint2 raw = *(const uint2*)(src + (size_t)idx[j] * DIM + t * 4);
        const float2 v0 = __half22float2(*(const __half2*)&raw.x);
        const float2 v1 = __half22float2(*(const __half2*)&raw.y);
        acc0 += v0.x; acc1 += v0.y; acc2 += v1.x; acc3 += v1.y;
    }
    if (RELU) {
        acc0 = fmaxf(acc0, 0.f); acc1 = fmaxf(acc1, 0.f);
        acc2 = fmaxf(acc2, 0.f); acc3 = fmaxf(acc3, 0.f);
    }
    uint2 packed;
    *(__half2*)&packed.x = __floats2half2_rn(acc0, acc1);
    *(__half2*)&packed.y = __floats2half2_rn(acc2, acc3);
    *(uint2*)(out + (size_t)atom * DIM + t * 4) = packed;
}

// ---------------- bond bias (fp16 output) ----------------
__global__ void bond_bias_kernel(const float* __restrict__ f_bonds, const int* __restrict__ a2b,
                                 const float* __restrict__ Wb, const float* __restrict__ b0,
                                 __half* __restrict__ dst)
{
    const int atom = blockIdx.x;
    const int t = threadIdx.x;
    __shared__ float bs[14];
    if (t < 14) {
        const int* idx = a2b + (size_t)atom * 6;
        float s = 0.f;
        #pragma unroll
        for (int j = 0; j < 6; j++) s += f_bonds[(size_t)idx[j] * 14 + t];
        bs[t] = fmaxf(s, 0.f);
    }
    __syncthreads();
    #pragma unroll
    for (int rr = 0; rr < 4; rr++) {
        int n = t + rr * 128;
        float acc = b0[n];
        #pragma unroll
        for (int k = 0; k < 14; k++) acc = fmaf(bs[k], Wb[k * DIM + n], acc);
        dst[(size_t)atom * DIM + n] = __float2half(acc);
    }
}

// ---------------- segment sum via atomics ----------------
__global__ void segment_atomic(const float* __restrict__ x, const int* __restrict__ mol_ids,
                               float* __restrict__ out, int n_mols)
{
    const int atom = blockIdx.x;
    const int mid = mol_ids[atom];
    if (mid < 0 || mid >= n_mols) return;
    const int t = threadIdx.x;
    #pragma unroll
    for (int rr = 0; rr < 4; rr++) {
        int n = t + rr * 128;
        atomicAdd(out + (size_t)mid * DIM + n, x[(size_t)atom * DIM + n]);
    }
}

extern "C" void kernel_launch(void* const* d_in, const int* in_sizes, int n_in,
                              void* d_out, int out_size)
{
    const float* f_atoms = (const float*)d_in[0];
    const float* f_bonds = (const float*)d_in[1];
    const int*   a2a     = (const int*)d_in[2];
    const int*   a2b     = (const int*)d_in[3];
    const int*   mol_ids = (const int*)d_in[4];
    const int base = n_in - 16;
    const float* W_i_w  = (const float*)d_in[base + 0];
    const float* W_i_b  = (const float*)d_in[base + 1];
    const float* Wh0_w  = (const float*)d_in[base + 2];
    const float* Wh0_b  = (const float*)d_in[base + 3];
    const float* Wh1_w  = (const float*)d_in[base + 4];
    const float* Wh1_b  = (const float*)d_in[base + 5];
    const float* Wh2_w  = (const float*)d_in[base + 6];
    const float* Wh2_b  = (const float*)d_in[base + 7];
    const float* Wah0_w = (const float*)d_in[base + 8];
    const float* Wah0_b = (const float*)d_in[base + 9];
    const float* Wah1_w = (const float*)d_in[base + 10];
    const float* Wah1_b = (const float*)d_in[base + 11];
    const float* Wah2_w = (const float*)d_in[base + 12];
    const float* Wah2_b = (const float*)d_in[base + 13];
    const float* W_o_w  = (const float*)d_in[base + 14];
    const float* W_o_b  = (const float*)d_in[base + 15];

    const int M      = in_sizes[0] / 133;
    const int n_mols = out_size / DIM;

    float *p_msg, *p_f32b;
    __half *p_biash, *p_pa, *p_msgh, *p_pg, *p_p0, *p_p1, *p_pcc, *p_wt;
    cudaGetSymbolAddress((void**)&p_msg,   g_msg);
    cudaGetSymbolAddress((void**)&p_f32b,  g_f32b);
    cudaGetSymbolAddress((void**)&p_biash, g_biash);
    cudaGetSymbolAddress((void**)&p_pa,    g_pa);
    cudaGetSymbolAddress((void**)&p_msgh,  g_msgh);
    cudaGetSymbolAddress((void**)&p_pg,    g_pg);
    cudaGetSymbolAddress((void**)&p_p0,    g_p0);
    cudaGetSymbolAddress((void**)&p_p1,    g_p1);
    cudaGetSymbolAddress((void**)&p_pcc,   g_pcc);
    cudaGetSymbolAddress((void**)&p_wt,    g_wt);

    // weight offsets in fp16 elements — matches prep_all order
    const size_t OFF_WI   = 0;
    const size_t OFF_WAH0 = 98304;
    const size_t OFF_WAH1 = 196608;
    const size_t OFF_WAH2 = 458752;
    const size_t OFF_WH0  = 720896;
    const size_t OFF_WH1  = 983040;
    const size_t OFF_WH2  = 1245184;
    const size_t OFF_WO   = 1507328;   // 512 x 1024 combined

    const int SMEM_BYTES = 110592;
    cudaFuncSetAttribute(gemm_mma<true,  true,  false>, cudaFuncAttributeMaxDynamicSharedMemorySize, SMEM_BYTES);
    cudaFuncSetAttribute(gemm_mma<true,  true,  true >, cudaFuncAttributeMaxDynamicSharedMemorySize, SMEM_BYTES);
    cudaFuncSetAttribute(gemm_mma<false, true,  true >, cudaFuncAttributeMaxDynamicSharedMemorySize, SMEM_BYTES);
    cudaFuncSetAttribute(gemm_mma<true,  false, true >, cudaFuncAttributeMaxDynamicSharedMemorySize, SMEM_BYTES);

    const dim3 gg(4, (M + 127) / 128);

    // launch 0: ALL prep fused
    prep_all<<<1024, 256>>>(f_atoms, W_i_w, Wah0_w, Wah1_w, Wah2_w,
                            Wh0_w, Wh1_w, Wh2_w, W_o_w,
                            p_wt, p_pa, M);

    // launches 1-3: cc chain (GEMMs — ncu capture lands here)
    gemm_mma<true, true, false><<<gg, 256, SMEM_BYTES>>>(
        p_pa, p_pa, 3, KPA, p_wt + OFF_WAH0, Wah0_b, nullptr, nullptr,
        nullptr, p_p0, M, KPA, 0);
    gemm_mma<true, true, false><<<gg, 256, SMEM_BYTES>>>(
        p_p0, p_p0, 8, 512, p_wt + OFF_WAH1, Wah1_b, nullptr, nullptr,
        nullptr, p_p1, M, 512, 0);
    gemm_mma<true, true, false><<<gg, 256, SMEM_BYTES>>>(
        p_p1, p_p1, 8, 512, p_wt + OFF_WAH2, Wah2_b, nullptr, nullptr,
        nullptr, p_pcc, M, 512, 0);

    // msg = relu(f_atoms @ W_i + b_i), row0 zeroed -> fp32 + fp16 mirror
    gemm_mma<true, true, true><<<gg, 256, SMEM_BYTES>>>(
        p_pa, p_pa, 3, KPA, p_wt + OFF_WI, W_i_b, nullptr, nullptr,
        p_msg, p_msgh, M, KPA, 1);

    bond_bias_kernel<<<M, 128>>>(f_bonds, a2b, Wh0_w + (size_t)DIM * DIM, Wh0_b, p_biash);

    for (int d = 0; d < 4; d++) {
        gather_h<true><<<M, 128>>>(p_msgh, a2a, p_pg);
        // t0 = split-free: gath @ Wh0_atom + bias map (fp16), relu
        gemm_mma<true, true, false><<<gg, 256, SMEM_BYTES>>>(
            p_pg, p_pg, 8, 512, p_wt + OFF_WH0, nullptr, nullptr, p_biash,
            nullptr, p_p0, M, 512, 0);
        gemm_mma<true, true, false><<<gg, 256, SMEM_BYTES>>>(
            p_p0, p_p0, 8, 512, p_wt + OFF_WH1, Wh1_b, nullptr, nullptr,
            nullptr, p_p1, M, 512, 0);
        // msg = t1 @ Wh2 + b2 + msg (fp32 residual + fp16 mirror, row0 zeroed)
        gemm_mma<false, true, true><<<gg, 256, SMEM_BYTES>>>(
            p_p1, p_p1, 8, 512, p_wt + OFF_WH2, Wh2_b, p_msg, nullptr,
            p_msg, p_msgh, M, 512, 1);
    }

    // a_message (NO relu) -> fp16
    gather_h<false><<<M, 128>>>(p_msgh, a2a, p_pg);

    cudaMemsetAsync(d_out, 0, (size_t)out_size * sizeof(float), 0);

    // out = relu([cc | a_message] @ W_o + b_o)   (fused K=1024 GEMM)
    gemm_mma<true, false, true><<<gg, 256, SMEM_BYTES>>>(
        p_pcc, p_pg, 8, 512, p_wt + OFF_WO, W_o_b, nullptr, nullptr,
        p_f32b, nullptr, M, 1024, 0);

    segment_atomic<<<M, 128>>>(p_f32b, mol_ids, (float*)d_out, n_mols);
}

// round 17
// speedup vs baseline: 3.0901x; 1.0769x over previous
#include <cuda_runtime.h>
#include <cuda_fp16.h>
#include <cstdint>
#include <cstddef>

#define DIM 512
#define MAXA 100000
#define KPA 192

// ---------------- scratch (static device globals; no allocation) ----------------
__device__ float g_msg [(size_t)MAXA * DIM];
__device__ float g_f32b[(size_t)MAXA * DIM];
// fp16 buffers
__device__ __align__(16) __half g_biash[(size_t)MAXA * DIM];
__device__ __align__(16) __half g_pa  [(size_t)MAXA * KPA];
__device__ __align__(16) __half g_msgh[(size_t)MAXA * DIM];   // fp16 mirror of msg
__device__ __align__(16) __half g_pg  [(size_t)MAXA * DIM];
__device__ __align__(16) __half g_p0  [(size_t)MAXA * DIM];
__device__ __align__(16) __half g_p1  [(size_t)MAXA * DIM];
__device__ __align__(16) __half g_pcc [(size_t)MAXA * DIM];
// transposed fp16 weights
__device__ __align__(16) __half g_wt[2031616];

// ---------------- helpers ----------------
__device__ __forceinline__ uint32_t s2u(const void* p) {
    uint32_t a;
    asm("{ .reg .u64 t; cvta.to.shared.u64 t, %1; cvt.u32.u64 %0, t; }" : "=r"(a) : "l"(p));
    return a;
}

#define CP16(dst, src) \
    asm volatile("cp.async.cg.shared.global [%0], [%1], 16;" :: "r"(dst), "l"(src) : "memory")
#define CP_COMMIT() asm volatile("cp.async.commit_group;" ::: "memory")
#define CP_WAIT1()  asm volatile("cp.async.wait_group 1;" ::: "memory")

#define LDSM4(r, addr) \
    asm volatile("ldmatrix.sync.aligned.m8n8.x4.shared.b16 {%0,%1,%2,%3}, [%4];" \
        : "=r"((r)[0]), "=r"((r)[1]), "=r"((r)[2]), "=r"((r)[3]) : "r"(addr))

#define MMA16816(d, a, b0, b1) \
    asm volatile("mma.sync.aligned.m16n8k16.row.col.f32.f16.f16.f32 " \
        "{%0,%1,%2,%3}, {%4,%5,%6,%7}, {%8,%9}, {%0,%1,%2,%3};" \
        : "+f"((d)[0]), "+f"((d)[1]), "+f"((d)[2]), "+f"((d)[3]) \
        : "r"((a)[0]), "r"((a)[1]), "r"((a)[2]), "r"((a)[3]), "r"(b0), "r"(b1))

// ---------------- fused prep: atoms fp16 + all weight transposes ----------------
// order/offsets: WI(192), WAH0(192), WAH1(512), WAH2(512), WH0(512), WH1(512),
//                WH2(512), WO(1024 = full W_o_w)
__global__ void prep_all(const float* __restrict__ fa,
    const float* __restrict__ W_i,  const float* __restrict__ Wah0,
    const float* __restrict__ Wah1, const float* __restrict__ Wah2,
    const float* __restrict__ Wh0,  const float* __restrict__ Wh1,
    const float* __restrict__ Wh2,  const float* __restrict__ Wo,
    __half* __restrict__ wt, __half* __restrict__ pa, int M)
{
    const int tid0 = blockIdx.x * blockDim.x + threadIdx.x;
    const int stride = gridDim.x * blockDim.x;

    for (int idx = tid0; idx < M * KPA; idx += stride) {
        int row = idx / KPA, k = idx - row * KPA;
        float v = (k < 133) ? fa[(size_t)row * 133 + k] : 0.f;
        pa[idx] = __float2half(v);
    }

    const float* srcs[8] = {W_i, Wah0, Wah1, Wah2, Wh0, Wh1, Wh2, Wo};
    const int    kre[8]  = {133, 133, 512, 512, 512, 512, 512, 1024};
    const int    kps[8]  = {KPA, KPA, 512, 512, 512, 512, 512, 1024};
    size_t off = 0;
    #pragma unroll 1
    for (int t = 0; t < 8; t++) {
        const int Kp = kps[t], total = 512 * Kp, kr = kre[t];
        const float* W = srcs[t];
        __half* out = wt + off;
        for (int idx = tid0; idx < total; idx += stride) {
            int n = idx / Kp, k = idx - n * Kp;
            float v = (k < kr) ? W[(size_t)k * 512 + n] : 0.f;
            out[idx] = __float2half(v);
        }
        off += total;
    }
}

// ---------------- HMMA GEMM: out = f([A|A2] @ W + bias + addf + addh), pure fp16 ------
// CTA tile 128M x 128N, BK=64, grid (4, ceil(M/128)), 512 threads, warp tile 16x64.
// 16 warps (grid 8x2), acc 32/thread -> 64-reg budget, 2 CTAs/SM = 8 warps/SMSP.
// 3-stage cp.async pipeline, ONE __syncthreads per chunk. smem 110592 B.
template<bool RELU_OUT, bool EMIT_H, bool EMIT_F>
__global__ void __launch_bounds__(512, 2) gemm_mma(
    const __half* __restrict__ A, const __half* __restrict__ A2, int nchA, int KpA,
    const __half* __restrict__ Wp,
    const float* __restrict__ bias,
    const float* __restrict__ addf, const __half* __restrict__ addh,
    float* __restrict__ Cf, __half* __restrict__ Cp,
    int M, int Kp, int zero_row0)
{
    extern __shared__ __align__(16) char smem[];
    const uint32_t sb = s2u(smem);
    const uint32_t RS = 144;
    const uint32_t B_OFF = 18432, STG = 36864;

    const int tid = threadIdx.x, lane = tid & 31, wid = tid >> 5;
    const int wm = wid >> 1, wn = wid & 1;    // warp grid 8x2, warp tile 16M x 64N
    const int row0 = blockIdx.y * 128, col0 = blockIdx.x * 128;
    const int nch = Kp >> 6;

    float acc[8][4];
    #pragma unroll
    for (int j = 0; j < 8; j++)
        #pragma unroll
        for (int q = 0; q < 4; q++) acc[j][q] = 0.f;

    // loaders: 4 threads/row (128 rows), 16 elems (32 B) each
    const int lr = tid >> 2, seg = (tid & 3) * 16;
    const int agrow = row0 + lr;
    const uint32_t dst = (uint32_t)lr * RS + (uint32_t)seg * 2;

    auto issue = [&](int c, int buf) {
        uint32_t base = sb + (uint32_t)buf * STG;
        if (agrow < M) {
            const __half* As = (c < nchA) ? A : A2;
            const int cc = (c < nchA) ? c : c - nchA;
            const __half* s = As + (size_t)agrow * KpA + cc * 64 + seg;
            uint32_t d = base + dst;
            CP16(d, s);  CP16(d + 16, s + 8);
        }
        {
            const __half* s = Wp + (size_t)(col0 + lr) * Kp + c * 64 + seg;
            uint32_t d = base + B_OFF + dst;
            CP16(d, s);  CP16(d + 16, s + 8);
        }
    };

    const uint32_t a_off = (uint32_t)(wm * 16 + (lane & 15)) * RS + (uint32_t)(lane >> 4) * 16;
    const uint32_t b_off = (uint32_t)(wn * 64 + (lane & 7) + ((lane >> 4) & 1) * 8) * RS
                           + (uint32_t)((lane >> 3) & 1) * 16;

    issue(0, 0);
    CP_COMMIT();
    if (nch > 1) issue(1, 1);
    CP_COMMIT();

    int stage = 0;
    for (int c = 0; c < nch; c++) {
        CP_WAIT1();
        __syncthreads();

        if (c + 2 < nch) issue(c + 2, (c + 2) % 3);
        CP_COMMIT();

        const uint32_t sbase = sb + (uint32_t)stage * STG;
        const uint32_t abase = sbase + a_off;
        const uint32_t bbase = sbase + B_OFF + b_off;
        #pragma unroll
        for (int ks = 0; ks < 4; ks++) {
            uint32_t ah[4];
            LDSM4(ah, abase + ks * 32);
            #pragma unroll
            for (int ntp = 0; ntp < 4; ntp++) {
                uint32_t bh[4];
                LDSM4(bh, bbase + ntp * 16 * RS + ks * 32);
                MMA16816(acc[ntp * 2 + 0], ah, bh[0], bh[1]);
                MMA16816(acc[ntp * 2 + 1], ah, bh[2], bh[3]);
            }
        }
        stage = (stage + 1 == 3) ? 0 : stage + 1;
    }

    // ---- epilogue ----
    const int g = lane >> 2, tg = lane & 3;
    #pragma unroll
    for (int nt = 0; nt < 8; nt++) {
        const int col = col0 + wn * 64 + nt * 8 + tg * 2;
        #pragma unroll
        for (int half = 0; half < 2; half++) {
            const int row = row0 + wm * 16 + g + half * 8;
            if (row >= M) continue;
            float v0 = acc[nt][half * 2 + 0];
            float v1 = acc[nt][half * 2 + 1];
            if (bias) {
                const float2 bv = *(const float2*)(bias + col);
                v0 += bv.x; v1 += bv.y;
            }
            if (addf) {
                const float2 av = *(const float2*)(addf + (size_t)row * DIM + col);
                v0 += av.x; v1 += av.y;
            }
            if (addh) {
                const float2 av = __half22float2(*(const __half2*)(addh + (size_t)row * DIM + col));
                v0 += av.x; v1 += av.y;
            }
            if (RELU_OUT) { v0 = fmaxf(v0, 0.f); v1 = fmaxf(v1, 0.f); }
            if (zero_row0 && row == 0) { v0 = 0.f; v1 = 0.f; }
            if (EMIT_F)
                *(float2*)(Cf + (size_t)row * DIM + col) = make_float2(v0, v1);
            if (EMIT_H)
                *(__half2*)(Cp + (size_t)row * DIM + col) = __floats2half2_rn(v0, v1);
        }
    }
}

// ---------------- gather-sum (fp16 src) + optional relu -> fp16 ----------------
template<bool RELU>
__global__ void gather_h(const __half* __restrict__ src, const int* __restrict__ a2a,
                         __half* __restrict__ out)
{
    const int atom = blockIdx.x;
    const int t = threadIdx.x;                 // 128 threads x 4 halves
    const int* idx = a2a + (size_t)atom * 6;
    float acc0 = 0.f, acc1 = 0.f, acc2 = 0.f, acc3 = 0.f;
    #pragma unroll
    for (int j = 0; j < 6; j++) {
        const uint2 raw = *(const uint2*)(src + (size_t)idx[j] * DIM + t * 4);
        const float2 v0 = __half22float2(*(const __half2*)&raw.x);
        const float2 v1 = __half22float2(*(const __half2*)&raw.y);
        acc0 += v0.x; acc1 += v0.y; acc2 += v1.x; acc3 += v1.y;
    }
    if (RELU) {
        acc0 = fmaxf(acc0, 0.f); acc1 = fmaxf(acc1, 0.f);
        acc2 = fmaxf(acc2, 0.f); acc3 = fmaxf(acc3, 0.f);
    }
    uint2 packed;
    *(__half2*)&packed.x = __floats2half2_rn(acc0, acc1);
    *(__half2*)&packed.y = __floats2half2_rn(acc2, acc3);
    *(uint2*)(out + (size_t)atom * DIM + t * 4) = packed;
}

// ---------------- bond bias (fp16 output) ----------------
__global__ void bond_bias_kernel(const float* __restrict__ f_bonds, const int* __restrict__ a2b,
                                 const float* __restrict__ Wb, const float* __restrict__ b0,
                                 __half* __restrict__ dst)
{
    const int atom = blockIdx.x;
    const int t = threadIdx.x;
    __shared__ float bs[14];
    if (t < 14) {
        const int* idx = a2b + (size_t)atom * 6;
        float s = 0.f;
        #pragma unroll
        for (int j = 0; j < 6; j++) s += f_bonds[(size_t)idx[j] * 14 + t];
        bs[t] = fmaxf(s, 0.f);
    }
    __syncthreads();
    #pragma unroll
    for (int rr = 0; rr < 4; rr++) {
        int n = t + rr * 128;
        float acc = b0[n];
        #pragma unroll
        for (int k = 0; k < 14; k++) acc = fmaf(bs[k], Wb[k * DIM + n], acc);
        dst[(size_t)atom * DIM + n] = __float2half(acc);
    }
}

// ---------------- segment sum via atomics ----------------
__global__ void segment_atomic(const float* __restrict__ x, const int* __restrict__ mol_ids,
                               float* __restrict__ out, int n_mols)
{
    const int atom = blockIdx.x;
    const int mid = mol_ids[atom];
    if (mid < 0 || mid >= n_mols) return;
    const int t = threadIdx.x;
    #pragma unroll
    for (int rr = 0; rr < 4; rr++) {
        int n = t + rr * 128;
        atomicAdd(out + (size_t)mid * DIM + n, x[(size_t)atom * DIM + n]);
    }
}

extern "C" void kernel_launch(void* const* d_in, const int* in_sizes, int n_in,
                              void* d_out, int out_size)
{
    const float* f_atoms = (const float*)d_in[0];
    const float* f_bonds = (const float*)d_in[1];
    const int*   a2a     = (const int*)d_in[2];
    const int*   a2b     = (const int*)d_in[3];
    const int*   mol_ids = (const int*)d_in[4];
    const int base = n_in - 16;
    const float* W_i_w  = (const float*)d_in[base + 0];
    const float* W_i_b  = (const float*)d_in[base + 1];
    const float* Wh0_w  = (const float*)d_in[base + 2];
    const float* Wh0_b  = (const float*)d_in[base + 3];
    const float* Wh1_w  = (const float*)d_in[base + 4];
    const float* Wh1_b  = (const float*)d_in[base + 5];
    const float* Wh2_w  = (const float*)d_in[base + 6];
    const float* Wh2_b  = (const float*)d_in[base + 7];
    const float* Wah0_w = (const float*)d_in[base + 8];
    const float* Wah0_b = (const float*)d_in[base + 9];
    const float* Wah1_w = (const float*)d_in[base + 10];
    const float* Wah1_b = (const float*)d_in[base + 11];
    const float* Wah2_w = (const float*)d_in[base + 12];
    const float* Wah2_b = (const float*)d_in[base + 13];
    const float* W_o_w  = (const float*)d_in[base + 14];
    const float* W_o_b  = (const float*)d_in[base + 15];

    const int M      = in_sizes[0] / 133;
    const int n_mols = out_size / DIM;

    float *p_msg, *p_f32b;
    __half *p_biash, *p_pa, *p_msgh, *p_pg, *p_p0, *p_p1, *p_pcc, *p_wt;
    cudaGetSymbolAddress((void**)&p_msg,   g_msg);
    cudaGetSymbolAddress((void**)&p_f32b,  g_f32b);
    cudaGetSymbolAddress((void**)&p_biash, g_biash);
    cudaGetSymbolAddress((void**)&p_pa,    g_pa);
    cudaGetSymbolAddress((void**)&p_msgh,  g_msgh);
    cudaGetSymbolAddress((void**)&p_pg,    g_pg);
    cudaGetSymbolAddress((void**)&p_p0,    g_p0);
    cudaGetSymbolAddress((void**)&p_p1,    g_p1);
    cudaGetSymbolAddress((void**)&p_pcc,   g_pcc);
    cudaGetSymbolAddress((void**)&p_wt,    g_wt);

    // weight offsets in fp16 elements — matches prep_all order
    const size_t OFF_WI   = 0;
    const size_t OFF_WAH0 = 98304;
    const size_t OFF_WAH1 = 196608;
    const size_t OFF_WAH2 = 458752;
    const size_t OFF_WH0  = 720896;
    const size_t OFF_WH1  = 983040;
    const size_t OFF_WH2  = 1245184;
    const size_t OFF_WO   = 1507328;   // 512 x 1024 combined

    const int SMEM_BYTES = 110592;
    cudaFuncSetAttribute(gemm_mma<true,  true,  false>, cudaFuncAttributeMaxDynamicSharedMemorySize, SMEM_BYTES);
    cudaFuncSetAttribute(gemm_mma<true,  true,  true >, cudaFuncAttributeMaxDynamicSharedMemorySize, SMEM_BYTES);
    cudaFuncSetAttribute(gemm_mma<false, true,  true >, cudaFuncAttributeMaxDynamicSharedMemorySize, SMEM_BYTES);
    cudaFuncSetAttribute(gemm_mma<true,  false, true >, cudaFuncAttributeMaxDynamicSharedMemorySize, SMEM_BYTES);

    const dim3 gg(4, (M + 127) / 128);

    // launch 0: ALL prep fused
    prep_all<<<1024, 256>>>(f_atoms, W_i_w, Wah0_w, Wah1_w, Wah2_w,
                            Wh0_w, Wh1_w, Wh2_w, W_o_w,
                            p_wt, p_pa, M);

    // launches 1-3: cc chain (GEMMs — ncu capture lands here)
    gemm_mma<true, true, false><<<gg, 512, SMEM_BYTES>>>(
        p_pa, p_pa, 3, KPA, p_wt + OFF_WAH0, Wah0_b, nullptr, nullptr,
        nullptr, p_p0, M, KPA, 0);
    gemm_mma<true, true, false><<<gg, 512, SMEM_BYTES>>>(
        p_p0, p_p0, 8, 512, p_wt + OFF_WAH1, Wah1_b, nullptr, nullptr,
        nullptr, p_p1, M, 512, 0);
    gemm_mma<true, true, false><<<gg, 512, SMEM_BYTES>>>(
        p_p1, p_p1, 8, 512, p_wt + OFF_WAH2, Wah2_b, nullptr, nullptr,
        nullptr, p_pcc, M, 512, 0);

    // msg = relu(f_atoms @ W_i + b_i), row0 zeroed -> fp32 + fp16 mirror
    gemm_mma<true, true, true><<<gg, 512, SMEM_BYTES>>>(
        p_pa, p_pa, 3, KPA, p_wt + OFF_WI, W_i_b, nullptr, nullptr,
        p_msg, p_msgh, M, KPA, 1);

    bond_bias_kernel<<<M, 128>>>(f_bonds, a2b, Wh0_w + (size_t)DIM * DIM, Wh0_b, p_biash);

    for (int d = 0; d < 4; d++) {
        gather_h<true><<<M, 128>>>(p_msgh, a2a, p_pg);
        // t0 = gath @ Wh0_atom + bias map (fp16), relu
        gemm_mma<true, true, false><<<gg, 512, SMEM_BYTES>>>(
            p_pg, p_pg, 8, 512, p_wt + OFF_WH0, nullptr, nullptr, p_biash,
            nullptr, p_p0, M, 512, 0);
        gemm_mma<true, true, false><<<gg, 512, SMEM_BYTES>>>(
            p_p0, p_p0, 8, 512, p_wt + OFF_WH1, Wh1_b, nullptr, nullptr,
            nullptr, p_p1, M, 512, 0);
        // msg = t1 @ Wh2 + b2 + msg (fp32 residual + fp16 mirror, row0 zeroed)
        gemm_mma<false, true, true><<<gg, 512, SMEM_BYTES>>>(
            p_p1, p_p1, 8, 512, p_wt + OFF_WH2, Wh2_b, p_msg, nullptr,
            p_msg, p_msgh, M, 512, 1);
    }

    // a_message (NO relu) -> fp16
    gather_h<false><<<M, 128>>>(p_msgh, a2a, p_pg);

    cudaMemsetAsync(d_out, 0, (size_t)out_size * sizeof(float), 0);

    // out = relu([cc | a_message] @ W_o + b_o)   (fused K=1024 GEMM)
    gemm_mma<true, false, true><<<gg, 512, SMEM_BYTES>>>(
        p_pcc, p_pg, 8, 512, p_wt + OFF_WO, W_o_b, nullptr, nullptr,
        p_f32b, nullptr, M, 1024, 0);

    segment_atomic<<<M, 128>>>(p_f32b, mol_ids, (float*)d_out, n_mols);
}